// round 14
// baseline (speedup 1.0000x reference)
#include <cuda_runtime.h>
#include <cuda_fp16.h>
#include <stdint.h>
#include <math.h>

// ---------------- problem constants ----------------
#define Bn   4
#define Cn   512
#define Hn   768
#define NHn  12
#define NEn  20
#define MMn  23
#define Pn   380
#define BPn  1520
#define QSn  128
#define EMBn 768
#define NBn  12
#define BLKn 64
#define NCLSn 97
#define POSn 128

static __device__ __constant__ float kNEG = -10000.0f;
#define SCALE_EMB 0.03608439182435161f   // 1/sqrt(768)

// ---------------- scratch ----------------
#define OFF_ENT_EMB 0UL
#define OFF_ENT_ATT (OFF_ENT_EMB + 1840UL*768)
#define OFF_ENT_Q   (OFF_ENT_ATT + 960UL*512)
#define OFF_HT_ATT  (OFF_ENT_Q   + 1840UL*128)
#define OFF_RS      (OFF_HT_ATT  + 1520UL*512)
#define OFF_HTQ     (OFF_RS      + 1520UL*768)
#define OFF_HS_ATT  (OFF_HTQ     + 1520UL*128)
#define OFF_TS_ATT  (OFF_HS_ATT  + 1520UL*768)
#define OFF_CAT_H   (OFF_TS_ATT  + 1520UL*768)
#define OFF_CAT_T   (OFF_CAT_H   + 1520UL*1536)
#define OFF_HS      (OFF_CAT_T   + 1520UL*1536)
#define OFF_TS      (OFF_HS      + 1520UL*768)
#define OFF_PAIRG   (OFF_TS      + 1520UL*768)
#define OFF_CATPP   (OFF_PAIRG   + 1520UL*768)
#define OFF_PAIR1   (OFF_CATPP   + 1520UL*1024)
#define OFF_QB      (OFF_PAIR1   + 1520UL*768)
#define OFF_KB      (OFF_QB      + 1520UL*768)
#define OFF_VB      (OFF_KB      + 1520UL*768)
#define OFF_SC      (OFF_VB      + 1520UL*768)
#define OFF_ATTO    (OFF_SC      + 4UL*380*380)
#define OFF_CATF    (OFF_ATTO    + 1520UL*768)
#define OFF_H1      (OFF_CATF    + 1520UL*2304)
#define OFF_WCAT    (OFF_H1      + 1520UL*768)
#define OFF_WQKV    (OFF_WCAT    + 2UL*1536*768)
#define OFF_WB      (OFF_WQKV    + 3UL*768*768)
#define OFF_WHF     (OFF_WB      + 2UL*768)          // 768*24576 u32 (half2-packed W)
#define SCRATCH_TOTAL (OFF_WHF   + 768UL*24576)

__device__ float g_scratch[SCRATCH_TOTAL];

// ---------------- helpers ----------------
__device__ __forceinline__ uint32_t f2h2(float lo, float hi) {
    __half2 h = __floats2half2_rn(lo, hi);
    return *(uint32_t*)&h;
}
__device__ __forceinline__ void mma_f16(float* c, const uint32_t* a, const uint32_t* b) {
    asm volatile("mma.sync.aligned.m16n8k16.row.col.f32.f16.f16.f32 "
        "{%0,%1,%2,%3}, {%4,%5,%6,%7}, {%8,%9}, {%0,%1,%2,%3};"
        : "+f"(c[0]), "+f"(c[1]), "+f"(c[2]), "+f"(c[3])
        : "r"(a[0]), "r"(a[1]), "r"(a[2]), "r"(a[3]), "r"(b[0]), "r"(b[1]));
}
__device__ __forceinline__ void cp16(void* s, const void* g, int sz) {
    uint32_t sa = (uint32_t)__cvta_generic_to_shared(s);
    asm volatile("cp.async.cg.shared.global [%0], [%1], 16, %2;" :: "r"(sa), "l"(g), "r"(sz));
}
__device__ __forceinline__ void cp4(void* s, const void* g, int sz) {
    uint32_t sa = (uint32_t)__cvta_generic_to_shared(s);
    asm volatile("cp.async.ca.shared.global [%0], [%1], 4, %2;" :: "r"(sa), "l"(g), "r"(sz));
}
__device__ __forceinline__ void cp_commit() { asm volatile("cp.async.commit_group;"); }
template<int Ng> __device__ __forceinline__ void cp_wait() {
    asm volatile("cp.async.wait_group %0;" :: "n"(Ng));
}

// ---------------- fp16 GEMM: 64x64xBK32, 256 thr (8 warps of 16x32), 3-stage cp.async ----------------
#define GT_BM 64
#define GT_BN 64
#define GT_BK 32
#define GT_SMEM (3 * 2304 * 2 * 4)

template<bool TRANSB, bool BIAS, bool TANH>
__global__ __launch_bounds__(256, 2)
void gemm_tc(const float* __restrict__ A, const float* __restrict__ Bm,
             const float* __restrict__ bias, float* __restrict__ C,
             int M, int N, int K, int lda, int ldb, int ldc,
             long sA, long sB, long sC, float alpha, long sBias)
{
    extern __shared__ float sm[];
    float* As = sm;                     // [3][64][36]
    float* Bs = sm + 3 * 2304;          // [3][32][72] (!T) or [3][64][36] (T)
    const int tid = threadIdx.x;
    const int wid = tid >> 5, lane = tid & 31;
    const int gid = lane >> 2, tig = lane & 3;
    const int m0 = blockIdx.y * GT_BM, n0 = blockIdx.x * GT_BN;
    A  += (long)blockIdx.z * sA;
    Bm += (long)blockIdx.z * sB;
    C  += (long)blockIdx.z * sC;
    if (BIAS) bias += (long)blockIdx.z * sBias;
    const int wm0 = (wid & 3) * 16, wn0 = (wid >> 2) * 32;
    float acc[4][4] = {};

    const int ar = tid >> 2, akc = (tid & 3) * 8;
    const int bkr = tid >> 3, bnc = (tid & 7) * 8;
    const bool a_ok = (m0 + ar) < M;
    const bool b4 = (!TRANSB) && (((ldb & 3) != 0) || ((N & 3) != 0));
    const int nk = (K + GT_BK - 1) / GT_BK;

    auto issueA = [&](int kt, int st) {
        float* dst = As + st * 2304 + ar * 36 + akc;
        const float* src = A + (long)(m0 + ar) * lda + kt * GT_BK + akc;
        #pragma unroll
        for (int q = 0; q < 2; ++q) {
            int sz = (a_ok && (kt * GT_BK + akc + 4 * q) < K) ? 16 : 0;
            cp16(dst + 4 * q, src + 4 * q, sz);
        }
    };
    auto issueB = [&](int kt, int st) {
        if (!TRANSB) {
            float* dst = Bs + st * 2304 + bkr * 72 + bnc;
            const float* src = Bm + (long)(kt * GT_BK + bkr) * ldb + n0 + bnc;
            const bool kok = (kt * GT_BK + bkr) < K;
            if (!b4) {
                #pragma unroll
                for (int q = 0; q < 2; ++q) {
                    int sz = (kok && (n0 + bnc + 4 * q) < N) ? 16 : 0;
                    cp16(dst + 4 * q, src + 4 * q, sz);
                }
            } else {
                #pragma unroll
                for (int e = 0; e < 8; ++e) {
                    int sz = (kok && (n0 + bnc + e) < N) ? 4 : 0;
                    cp4(dst + e, src + e, sz);
                }
            }
        } else {
            float* dst = Bs + st * 2304 + ar * 36 + akc;
            const float* src = Bm + (long)(n0 + ar) * ldb + kt * GT_BK + akc;
            const bool nok = (n0 + ar) < N;
            #pragma unroll
            for (int q = 0; q < 2; ++q) {
                int sz = (nok && (kt * GT_BK + akc + 4 * q) < K) ? 16 : 0;
                cp16(dst + 4 * q, src + 4 * q, sz);
            }
        }
    };

    issueA(0, 0); issueB(0, 0); cp_commit();
    if (nk > 1) { issueA(1, 1); issueB(1, 1); }
    cp_commit();

    int st = 0;
    for (int kt = 0; kt < nk; ++kt) {
        cp_wait<1>();
        __syncthreads();
        const int ktn = kt + 2;
        if (ktn < nk) {
            const int stn = (st + 2 >= 3) ? st - 1 : st + 2;
            issueA(ktn, stn); issueB(ktn, stn);
        }
        cp_commit();
        const float* Ac = As + st * 2304;
        const float* Bc = Bs + st * 2304;
        #pragma unroll
        for (int kk = 0; kk < GT_BK; kk += 16) {
            const int k0 = kk + tig * 2;
            uint32_t af[4], bf[4][2];
            {
                const float* r0 = Ac + (wm0 + gid) * 36;
                const float* r1 = Ac + (wm0 + 8 + gid) * 36;
                af[0] = f2h2(r0[k0], r0[k0 + 1]);
                af[1] = f2h2(r1[k0], r1[k0 + 1]);
                af[2] = f2h2(r0[k0 + 8], r0[k0 + 9]);
                af[3] = f2h2(r1[k0 + 8], r1[k0 + 9]);
            }
            #pragma unroll
            for (int nf = 0; nf < 4; ++nf) {
                const int c = wn0 + nf * 8 + gid;
                if (!TRANSB) {
                    bf[nf][0] = f2h2(Bc[k0 * 72 + c],       Bc[(k0 + 1) * 72 + c]);
                    bf[nf][1] = f2h2(Bc[(k0 + 8) * 72 + c], Bc[(k0 + 9) * 72 + c]);
                } else {
                    const float* rc = Bc + c * 36;
                    bf[nf][0] = f2h2(rc[k0], rc[k0 + 1]);
                    bf[nf][1] = f2h2(rc[k0 + 8], rc[k0 + 9]);
                }
            }
            #pragma unroll
            for (int nf = 0; nf < 4; ++nf)
                mma_f16(acc[nf], af, bf[nf]);
        }
        st = (st + 1 >= 3) ? 0 : st + 1;
    }
    // ---- epilogue ----
    #pragma unroll
    for (int nf = 0; nf < 4; ++nf) {
        const int r = m0 + wm0 + gid;
        const int c = n0 + wn0 + nf * 8 + tig * 2;
        #pragma unroll
        for (int half = 0; half < 2; ++half) {
            const int rr = r + half * 8;
            if (rr >= M) continue;
            #pragma unroll
            for (int j = 0; j < 2; ++j) {
                const int cc = c + j;
                if (cc >= N) continue;
                float v = acc[nf][half * 2 + j] * alpha;
                if (BIAS) v += bias[cc];
                if (TANH) v = tanhf(v);
                C[(long)rr * ldc + cc] = v;
            }
        }
    }
}

// ---------------- W pre-convert: fp32 [49152][768] -> half2-packed [768][32][768] ----------------
__global__ __launch_bounds__(256)
void conv_w_k(const float* __restrict__ W, uint32_t* __restrict__ Whf)
{
    const int t = blockIdx.x;
    const int tid = threadIdx.x;
    const float* Wt = W + (long)t * 64 * 768;
    uint32_t* Dt = Whf + (long)t * 24576;
    #pragma unroll 1
    for (int p = 0; p < 32; ++p) {
        const float* r0 = Wt + (2 * p) * 768;
        const float* r1 = Wt + (2 * p + 1) * 768;
        #pragma unroll
        for (int j = 0; j < 3; ++j) {
            const int c = tid + j * 256;
            Dt[p * 768 + c] = f2h2(r0[c], r1[c]);
        }
    }
}

// ---------------- bilinear: fp16 mma, pre-packed half2 W, 512 thr, M-tile 128 ----------------
#define BL_WSTRIDE 72
#define BL_WSTAGE  (32 * BL_WSTRIDE)
#define BL_SMEM    ((2*128*68 + 4*BL_WSTAGE) * 4)
__global__ __launch_bounds__(512)
void bilinear_tc(const float* __restrict__ Hs, const float* __restrict__ Ts,
                 const uint32_t* __restrict__ Whf, const float* __restrict__ bias,
                 float* __restrict__ C, int M)
{
    extern __shared__ float sm[];
    float* bh = sm;                      // [128][68]
    float* bt = sm + 128 * 68;           // [128][68]
    uint32_t* Ws = (uint32_t*)(sm + 2 * 128 * 68);   // [4][32][72]
    const int tid = threadIdx.x;
    const int wid = tid >> 5, lane = tid & 31;
    const int gid = lane >> 2, tig = lane & 3;
    const int m0 = blockIdx.y * 128, n0 = blockIdx.x * 64;
    const int wm0 = (wid & 3) * 32, wn0 = (wid >> 2) * 16;   // 16 warps: 4m x 4n
    float acc[2][2][4] = {};
    const int lr = tid >> 2, lc = (tid & 3) * 16;            // HT loads: 128 rows
    const bool lok = (m0 + lr) < M;
    const int wr = tid >> 2, wq = tid & 3;                   // W loads: threads 0..127
    uint32_t btf[2][4][4];

#define LOADHT(nb_) { \
    const float* hp = Hs + (long)(m0 + lr) * 768 + (nb_) * 64 + lc; \
    const float* tp = Ts + (long)(m0 + lr) * 768 + (nb_) * 64 + lc; \
    _Pragma("unroll") for (int q_ = 0; q_ < 4; ++q_) { \
        float4 hv = lok ? *(const float4*)(hp + 4 * q_) : make_float4(0, 0, 0, 0); \
        float4 tv = lok ? *(const float4*)(tp + 4 * q_) : make_float4(0, 0, 0, 0); \
        *(float4*)&bh[lr * 68 + lc + 4 * q_] = hv; \
        *(float4*)&bt[lr * 68 + lc + 4 * q_] = tv; } }

#define ISSUEW(t_, st_) { \
    if (tid < 128) { \
        uint32_t* dst_ = Ws + (st_) * BL_WSTAGE + wr * BL_WSTRIDE + wq * 16; \
        const uint32_t* src_ = Whf + (long)(t_) * 24576 + wr * 768 + n0 + wq * 16; \
        cp16(dst_, src_, 16); cp16(dst_ + 4, src_ + 4, 16); \
        cp16(dst_ + 8, src_ + 8, 16); cp16(dst_ + 12, src_ + 12, 16); } }

#define CACHEBT() { \
    _Pragma("unroll") for (int mf_ = 0; mf_ < 2; ++mf_) { const int r0_ = wm0 + mf_ * 16; \
        _Pragma("unroll") for (int j0_ = 0; j0_ < 4; ++j0_) { \
            const int k0_ = j0_ * 16 + tig * 2; \
            btf[mf_][j0_][0] = f2h2(bt[(r0_ + gid) * 68 + k0_],     bt[(r0_ + gid) * 68 + k0_ + 1]); \
            btf[mf_][j0_][1] = f2h2(bt[(r0_ + 8 + gid) * 68 + k0_], bt[(r0_ + 8 + gid) * 68 + k0_ + 1]); \
            btf[mf_][j0_][2] = f2h2(bt[(r0_ + gid) * 68 + k0_ + 8], bt[(r0_ + gid) * 68 + k0_ + 9]); \
            btf[mf_][j0_][3] = f2h2(bt[(r0_ + 8 + gid) * 68 + k0_ + 8], bt[(r0_ + 8 + gid) * 68 + k0_ + 9]); } } }

    LOADHT(0);
    ISSUEW(0, 0); cp_commit();
    ISSUEW(1, 1); cp_commit();
    ISSUEW(2, 2); cp_commit();
    __syncthreads();
    CACHEBT();

    for (int t = 0; t < NBn * 64; ++t) {
        const int st = t & 3;
        cp_wait<2>();
        __syncthreads();
        if (t + 3 < NBn * 64) { ISSUEW(t + 3, (t + 3) & 3); }
        cp_commit();
        const uint32_t* Wc = Ws + st * BL_WSTAGE;
        const int i = t & 63;
        float D[2][2][4] = {};
        #pragma unroll
        for (int j0 = 0; j0 < 4; ++j0) {
            uint32_t bfp[2][2];
            #pragma unroll
            for (int nf = 0; nf < 2; ++nf) {
                const int c = wn0 + nf * 8 + gid;
                bfp[nf][0] = Wc[(j0 * 8 + tig) * BL_WSTRIDE + c];
                bfp[nf][1] = Wc[(j0 * 8 + tig + 4) * BL_WSTRIDE + c];
            }
            #pragma unroll
            for (int mf = 0; mf < 2; ++mf)
                #pragma unroll
                for (int nf = 0; nf < 2; ++nf)
                    mma_f16(D[mf][nf], btf[mf][j0], bfp[nf]);
        }
        #pragma unroll
        for (int mf = 0; mf < 2; ++mf) {
            const float b0 = bh[(wm0 + mf * 16 + gid) * 68 + i];
            const float b1 = bh[(wm0 + mf * 16 + 8 + gid) * 68 + i];
            #pragma unroll
            for (int nf = 0; nf < 2; ++nf) {
                acc[mf][nf][0] = fmaf(b0, D[mf][nf][0], acc[mf][nf][0]);
                acc[mf][nf][1] = fmaf(b0, D[mf][nf][1], acc[mf][nf][1]);
                acc[mf][nf][2] = fmaf(b1, D[mf][nf][2], acc[mf][nf][2]);
                acc[mf][nf][3] = fmaf(b1, D[mf][nf][3], acc[mf][nf][3]);
            }
        }
        if ((t & 63) == 63 && t + 1 < NBn * 64) {
            __syncthreads();
            LOADHT((t + 1) >> 6);
            __syncthreads();
            CACHEBT();
        }
    }
#undef LOADHT
#undef ISSUEW
#undef CACHEBT
    #pragma unroll
    for (int mf = 0; mf < 2; ++mf) {
        #pragma unroll
        for (int nf = 0; nf < 2; ++nf) {
            const int r = m0 + wm0 + mf * 16 + gid;
            const int c = n0 + wn0 + nf * 8 + tig * 2;
            if (r < M) {
                C[(long)r * 768 + c]     = acc[mf][nf][0] + bias[c];
                C[(long)r * 768 + c + 1] = acc[mf][nf][1] + bias[c + 1];
            }
            if (r + 8 < M) {
                C[(long)(r + 8) * 768 + c]     = acc[mf][nf][2] + bias[c];
                C[(long)(r + 8) * 768 + c + 1] = acc[mf][nf][3] + bias[c + 1];
            }
        }
    }
}

// ---------------- small fused kernels ----------------
__global__ void ent_emb_k(const float* __restrict__ seq, const int* __restrict__ midx,
                          const float* __restrict__ mmask, float* __restrict__ ent_emb)
{
    const int blk = blockIdx.x;
    const int b = blk / (MMn * NEn);
    const int idx = midx[blk];
    const float mask = mmask[blk];
    const float* src = seq + ((long)b * Cn + idx) * Hn;
    float* dst = ent_emb + (long)blk * Hn;
    for (int h = threadIdx.x; h < Hn; h += 256) dst[h] = mask * src[h];
}

__global__ void ent_att_k(const float* __restrict__ att, const int* __restrict__ midx,
                          const float* __restrict__ mmask, float* __restrict__ ent_att)
{
    const int blk = blockIdx.x;
    const int nh = blk % NHn;
    const int e  = (blk / NHn) % NEn;
    const int b  = blk / (NHn * NEn);
    const int c  = threadIdx.x;
    const int* mi = midx + (b * NEn + e) * MMn;
    const float* mk = mmask + (b * NEn + e) * MMn;
    float cnt = 0.f, s = 0.f;
    for (int m = 0; m < MMn; ++m) {
        const float w = mk[m];
        cnt += w;
        s += w * att[(((long)b * NHn + nh) * Cn + mi[m]) * Cn + c];
    }
    ent_att[(long)blk * Cn + c] = s / cnt;
}

__global__ void ht_att_k(const float* __restrict__ ent_att, const int* __restrict__ hts,
                         float* __restrict__ ht_att)
{
    const int bp = blockIdx.x;
    const int b = bp / Pn;
    const int hi = hts[bp * 2], ti = hts[bp * 2 + 1];
    const int c = threadIdx.x;
    const float* ha = ent_att + (long)(b * NEn + hi) * NHn * Cn;
    const float* ta = ent_att + (long)(b * NEn + ti) * NHn * Cn;
    float v = 0.f;
    #pragma unroll
    for (int nh = 0; nh < NHn; ++nh) v += ha[nh * Cn + c] * ta[nh * Cn + c];
    v *= (1.f / 12.f);
    __shared__ float red[512];
    red[c] = v; __syncthreads();
    for (int s = 256; s > 0; s >>= 1) { if (c < s) red[c] += red[c + s]; __syncthreads(); }
    ht_att[(long)bp * Cn + c] = v / (red[0] + 1e-5f);
}

__global__ void pool_attn_k(const float* __restrict__ htq, const float* __restrict__ ent_q,
                            const float* __restrict__ ent_emb, const float* __restrict__ mmask,
                            const int* __restrict__ hts, float* __restrict__ hs_att,
                            float* __restrict__ ts_att)
{
    const int bp = blockIdx.x;
    const int side = blockIdx.y;
    const int b = bp / Pn;
    const int e = hts[bp * 2 + side];
    __shared__ float qs[QSn];
    __shared__ float gs[MMn];
    const int tid = threadIdx.x;
    if (tid < QSn) qs[tid] = htq[(long)bp * QSn + tid];
    __syncthreads();
    if (tid < MMn) {
        const float* eq = ent_q + ((long)(b * NEn + e) * MMn + tid) * QSn;
        float d = 0.f;
        for (int i = 0; i < QSn; ++i) d += qs[i] * eq[i];
        const float mk = mmask[(b * NEn + e) * MMn + tid];
        gs[tid] = (mk > 0.f) ? d * SCALE_EMB : kNEG;
    }
    __syncthreads();
    float mx = -1e30f;
    for (int m = 0; m < MMn; ++m) mx = fmaxf(mx, gs[m]);
    float w[MMn]; float ssum = 0.f;
    for (int m = 0; m < MMn; ++m) { w[m] = expf(gs[m] - mx); ssum += w[m]; }
    const float inv = 1.f / ssum;
    const float* emb = ent_emb + (long)(b * NEn + e) * MMn * Hn;
    float* out = (side ? ts_att : hs_att) + (long)bp * Hn;
    for (int h = tid; h < Hn; h += 256) {
        float acc2 = 0.f;
        for (int m = 0; m < MMn; ++m) acc2 += w[m] * emb[m * Hn + h];
        out[h] = acc2 * inv;
    }
}

__global__ void cat2_k(const float* __restrict__ hs_att, const float* __restrict__ ts_att,
                       const float* __restrict__ rs, float* __restrict__ cat_h,
                       float* __restrict__ cat_t)
{
    const long r = blockIdx.x;
    for (int h = threadIdx.x; h < Hn; h += 256) {
        const float rv = rs[r * Hn + h];
        cat_h[r * 1536 + h]       = hs_att[r * Hn + h];
        cat_h[r * 1536 + 768 + h] = rv;
        cat_t[r * 1536 + h]       = ts_att[r * Hn + h];
        cat_t[r * 1536 + 768 + h] = rv;
    }
}

__global__ void catpp_k(const float* __restrict__ pairg, const float* __restrict__ pos_emb,
                        const int* __restrict__ hts, float* __restrict__ catpp)
{
    const long r = blockIdx.x;
    const int hi = hts[r * 2], ti = hts[r * 2 + 1];
    if (threadIdx.x < POSn) {
        catpp[r * 1024 + threadIdx.x]       = pos_emb[hi * POSn + threadIdx.x];
        catpp[r * 1024 + 896 + threadIdx.x] = pos_emb[ti * POSn + threadIdx.x];
    }
    for (int h = threadIdx.x; h < Hn; h += 256)
        catpp[r * 1024 + 128 + h] = pairg[r * Hn + h];
}

__global__ void pair_softmax_k(float* __restrict__ sc, const float* __restrict__ vis)
{
    const long bp = blockIdx.x;
    float* row = sc + bp * Pn;
    const float* vr = vis + bp * Pn;
    const int tid = threadIdx.x;
    __shared__ float red[128];
    float mx = -1e30f;
    for (int q = tid; q < Pn; q += 128) {
        const float v = (vr[q] > 0.f) ? row[q] : kNEG;
        mx = fmaxf(mx, v);
    }
    red[tid] = mx; __syncthreads();
    for (int s = 64; s > 0; s >>= 1) { if (tid < s) red[tid] = fmaxf(red[tid], red[tid + s]); __syncthreads(); }
    mx = red[0]; __syncthreads();
    float sum = 0.f;
    for (int q = tid; q < Pn; q += 128) {
        const float v = (vr[q] > 0.f) ? row[q] : kNEG;
        sum += expf(v - mx);
    }
    red[tid] = sum; __syncthreads();
    for (int s = 64; s > 0; s >>= 1) { if (tid < s) red[tid] += red[tid + s]; __syncthreads(); }
    const float inv = 1.f / red[0];
    for (int q = tid; q < Pn; q += 128) {
        const float v = (vr[q] > 0.f) ? row[q] : kNEG;
        row[q] = expf(v - mx) * inv;
    }
}

__global__ void catfeat_k(const float* __restrict__ hs, const float* __restrict__ ts,
                          const float* __restrict__ pair1, const float* __restrict__ atto,
                          float* __restrict__ catf)
{
    const long r = blockIdx.x;
    for (int h = threadIdx.x; h < Hn; h += 256) {
        catf[r * 2304 + h]        = hs[r * Hn + h];
        catf[r * 2304 + 768 + h]  = ts[r * Hn + h];
        catf[r * 2304 + 1536 + h] = pair1[r * Hn + h] + atto[r * Hn + h];
    }
}

// ---------------- launcher ----------------
extern "C" void kernel_launch(void* const* d_in, const int* in_sizes, int n_in,
                              void* d_out, int out_size)
{
    (void)in_sizes; (void)n_in; (void)out_size;
    const float* seq   = (const float*)d_in[0];
    const float* att   = (const float*)d_in[1];
    const int*   midx  = (const int*)  d_in[2];
    const float* mmask = (const float*)d_in[3];
    const int*   hts   = (const int*)  d_in[4];
    const float* vis   = (const float*)d_in[5];
    const float* Wcq = (const float*)d_in[6],  *bcq = (const float*)d_in[7];
    const float* Weq = (const float*)d_in[8],  *beq = (const float*)d_in[9];
    const float* Whe = (const float*)d_in[10], *bhe = (const float*)d_in[11];
    const float* Wte = (const float*)d_in[12], *bte = (const float*)d_in[13];
    const float* Wbl = (const float*)d_in[14], *bbl = (const float*)d_in[15];
    const float* Wpp = (const float*)d_in[16], *bpp = (const float*)d_in[17];
    const float* Wgq = (const float*)d_in[18];
    const float* Wgk = (const float*)d_in[19];
    const float* Wgv = (const float*)d_in[20];
    const float* Wp1 = (const float*)d_in[21], *bp1 = (const float*)d_in[22];
    const float* Wp2 = (const float*)d_in[23], *bp2 = (const float*)d_in[24];
    const float* pos = (const float*)d_in[25];
    float* out = (float*)d_out;

    float* base = nullptr;
    cudaGetSymbolAddress((void**)&base, g_scratch);
    float* ent_emb = base + OFF_ENT_EMB;
    float* ent_att = base + OFF_ENT_ATT;
    float* ent_q   = base + OFF_ENT_Q;
    float* ht_att  = base + OFF_HT_ATT;
    float* rs      = base + OFF_RS;
    float* htqb    = base + OFF_HTQ;
    float* hs_att  = base + OFF_HS_ATT;
    float* ts_att  = base + OFF_TS_ATT;
    float* cat_h   = base + OFF_CAT_H;
    float* hs_t    = base + OFF_HS;
    float* ts_t    = base + OFF_TS;
    float* pairg   = base + OFF_PAIRG;
    float* catpp   = base + OFF_CATPP;
    float* pair1   = base + OFF_PAIR1;
    float* qb      = base + OFF_QB;
    float* kb      = base + OFF_KB;
    float* vb      = base + OFF_VB;
    float* scb     = base + OFF_SC;
    float* atto    = base + OFF_ATTO;
    float* catf    = base + OFF_CATF;
    float* h1      = base + OFF_H1;
    float* wcat    = base + OFF_WCAT;
    float* wqkv    = base + OFF_WQKV;
    float* wb      = base + OFF_WB;
    uint32_t* whf  = (uint32_t*)(base + OFF_WHF);

    cudaFuncSetAttribute(gemm_tc<false,false,false>, cudaFuncAttributeMaxDynamicSharedMemorySize, GT_SMEM);
    cudaFuncSetAttribute(gemm_tc<false,true,false>,  cudaFuncAttributeMaxDynamicSharedMemorySize, GT_SMEM);
    cudaFuncSetAttribute(gemm_tc<false,true,true>,   cudaFuncAttributeMaxDynamicSharedMemorySize, GT_SMEM);
    cudaFuncSetAttribute(gemm_tc<true,false,false>,  cudaFuncAttributeMaxDynamicSharedMemorySize, GT_SMEM);
    cudaFuncSetAttribute(bilinear_tc, cudaFuncAttributeMaxDynamicSharedMemorySize, BL_SMEM);

    // 0) pack batched weights/biases; pre-convert bilinear W to half2 layout
    cudaMemcpyAsync(wcat,              Whe, 1536UL*768*4, cudaMemcpyDeviceToDevice);
    cudaMemcpyAsync(wcat + 1536UL*768, Wte, 1536UL*768*4, cudaMemcpyDeviceToDevice);
    cudaMemcpyAsync(wqkv,              Wgq, 768UL*768*4,  cudaMemcpyDeviceToDevice);
    cudaMemcpyAsync(wqkv + 768UL*768,  Wgk, 768UL*768*4,  cudaMemcpyDeviceToDevice);
    cudaMemcpyAsync(wqkv + 2UL*768*768,Wgv, 768UL*768*4,  cudaMemcpyDeviceToDevice);
    cudaMemcpyAsync(wb,                bhe, 768UL*4,      cudaMemcpyDeviceToDevice);
    cudaMemcpyAsync(wb + 768,          bte, 768UL*4,      cudaMemcpyDeviceToDevice);
    conv_w_k<<<768, 256>>>(Wbl, whf);

    // 1) entity gathers
    ent_emb_k<<<Bn * NEn * MMn, 256>>>(seq, midx, mmask, ent_emb);
    ent_att_k<<<Bn * NEn * NHn, 512>>>(att, midx, mmask, ent_att);
    // 2) pair context attention
    ht_att_k<<<BPn, 512>>>(ent_att, hts, ht_att);
    // 3) rs = ht_att @ seq (batched)
    gemm_tc<false,false,false><<<dim3(12, 6, 4), 256, GT_SMEM>>>(ht_att, seq, nullptr, rs,
        Pn, Hn, Cn, Cn, Hn, Hn, 380L*512, 512L*768, 380L*768, 1.f, 0L);
    // 4) htq, ent_q
    gemm_tc<false,true,false><<<dim3(2, 24, 1), 256, GT_SMEM>>>(rs, Wcq, bcq, htqb,
        BPn, QSn, Hn, Hn, QSn, QSn, 0, 0, 0, 1.f, 0L);
    gemm_tc<false,true,false><<<dim3(2, 29, 1), 256, GT_SMEM>>>(ent_emb, Weq, beq, ent_q,
        1840, QSn, Hn, Hn, QSn, QSn, 0, 0, 0, 1.f, 0L);
    // 5) mention-pool softmax
    pool_attn_k<<<dim3(BPn, 2), 256>>>(htqb, ent_q, ent_emb, mmask, hts, hs_att, ts_att);
    // 6) hs/ts projections — ONE z=2 batched launch (per-z bias)
    cat2_k<<<BPn, 256>>>(hs_att, ts_att, rs, cat_h, base + OFF_CAT_T);
    gemm_tc<false,true,true><<<dim3(12, 24, 2), 256, GT_SMEM>>>(cat_h, wcat, wb, hs_t,
        BPn, EMBn, 1536, 1536, EMBn, EMBn, 1520L*1536, 1536L*768, 1520L*768, 1.f, 768L);
    // 7) grouped bilinear (fp16 mma, pre-packed W)
    bilinear_tc<<<dim3(12, 12), 512, BL_SMEM>>>(hs_t, ts_t, whf, bbl, pairg, BPn);
    // 8) pos concat + Wpp
    catpp_k<<<BPn, 256>>>(pairg, pos, hts, catpp);
    gemm_tc<false,true,true><<<dim3(12, 24, 1), 256, GT_SMEM>>>(catpp, Wpp, bpp, pair1,
        BPn, EMBn, 1024, 1024, EMBn, EMBn, 0, 0, 0, 1.f, 0L);
    // 9) pair-graph attention: q/k/v in ONE batched launch (z=3)
    gemm_tc<false,false,false><<<dim3(12, 24, 3), 256, GT_SMEM>>>(pair1, wqkv, nullptr, qb,
        BPn, EMBn, EMBn, EMBn, EMBn, EMBn, 0, 768L*768, 1520L*768, 1.f, 0L);
    gemm_tc<true,false,false><<<dim3(6, 6, 4), 256, GT_SMEM>>>(qb, kb, nullptr, scb,
        Pn, Pn, EMBn, EMBn, EMBn, Pn, 380L*768, 380L*768, 380L*380, SCALE_EMB, 0L);
    pair_softmax_k<<<BPn, 128>>>(scb, vis);
    gemm_tc<false,false,false><<<dim3(12, 6, 4), 256, GT_SMEM>>>(scb, vb, nullptr, atto,
        Pn, EMBn, Pn, Pn, EMBn, EMBn, 380L*380, 380L*768, 380L*768, 1.f, 0L);
    // 10) classifier head
    catfeat_k<<<BPn, 256>>>(hs_t, ts_t, pair1, atto, catf);
    gemm_tc<false,true,true><<<dim3(12, 24, 1), 256, GT_SMEM>>>(catf, Wp1, bp1, h1,
        BPn, EMBn, 2304, 2304, EMBn, EMBn, 0, 0, 0, 1.f, 0L);
    gemm_tc<false,true,false><<<dim3(2, 24, 1), 256, GT_SMEM>>>(h1, Wp2, bp2, out,
        BPn, NCLSn, EMBn, EMBn, NCLSn, NCLSn, 0, 0, 0, 1.f, 0L);
}

// round 15
// speedup vs baseline: 1.1033x; 1.1033x over previous
#include <cuda_runtime.h>
#include <cuda_fp16.h>
#include <stdint.h>
#include <math.h>

// ---------------- problem constants ----------------
#define Bn   4
#define Cn   512
#define Hn   768
#define NHn  12
#define NEn  20
#define MMn  23
#define Pn   380
#define BPn  1520
#define QSn  128
#define EMBn 768
#define NBn  12
#define BLKn 64
#define NCLSn 97
#define POSn 128

static __device__ __constant__ float kNEG = -10000.0f;
#define SCALE_EMB 0.03608439182435161f   // 1/sqrt(768)

// ---------------- scratch ----------------
#define OFF_ENT_EMB 0UL
#define OFF_ENT_ATT (OFF_ENT_EMB + 1840UL*768)
#define OFF_ENT_Q   (OFF_ENT_ATT + 960UL*512)
#define OFF_HT_ATT  (OFF_ENT_Q   + 1840UL*128)
#define OFF_RS      (OFF_HT_ATT  + 1520UL*512)
#define OFF_HTQ     (OFF_RS      + 1520UL*768)
#define OFF_HS_ATT  (OFF_HTQ     + 1520UL*128)
#define OFF_TS_ATT  (OFF_HS_ATT  + 1520UL*768)
#define OFF_CAT_H   (OFF_TS_ATT  + 1520UL*768)
#define OFF_CAT_T   (OFF_CAT_H   + 1520UL*1536)
#define OFF_HS      (OFF_CAT_T   + 1520UL*1536)
#define OFF_TS      (OFF_HS      + 1520UL*768)
#define OFF_PAIRG   (OFF_TS      + 1520UL*768)
#define OFF_CATPP   (OFF_PAIRG   + 1520UL*768)
#define OFF_PAIR1   (OFF_CATPP   + 1520UL*1024)
#define OFF_QB      (OFF_PAIR1   + 1520UL*768)
#define OFF_KB      (OFF_QB      + 1520UL*768)
#define OFF_VB      (OFF_KB      + 1520UL*768)
#define OFF_SC      (OFF_VB      + 1520UL*768)
#define OFF_ATTO    (OFF_SC      + 4UL*380*380)
#define OFF_CATF    (OFF_ATTO    + 1520UL*768)
#define OFF_H1      (OFF_CATF    + 1520UL*2304)
#define OFF_WCAT    (OFF_H1      + 1520UL*768)
#define OFF_WQKV    (OFF_WCAT    + 2UL*1536*768)
#define OFF_WB      (OFF_WQKV    + 3UL*768*768)
#define OFF_WHF     (OFF_WB      + 2UL*768)          // 768*24576 u32 (half2-packed W)
#define SCRATCH_TOTAL (OFF_WHF   + 768UL*24576)

__device__ float g_scratch[SCRATCH_TOTAL];

// ---------------- helpers ----------------
__device__ __forceinline__ uint32_t f2tf32(float x) {
    uint32_t r; asm("cvt.rna.tf32.f32 %0, %1;" : "=r"(r) : "f"(x)); return r;
}
__device__ __forceinline__ void mma_tf32(float* c, const uint32_t* a, const uint32_t* b) {
    asm volatile("mma.sync.aligned.m16n8k8.row.col.f32.tf32.tf32.f32 "
        "{%0,%1,%2,%3}, {%4,%5,%6,%7}, {%8,%9}, {%0,%1,%2,%3};"
        : "+f"(c[0]), "+f"(c[1]), "+f"(c[2]), "+f"(c[3])
        : "r"(a[0]), "r"(a[1]), "r"(a[2]), "r"(a[3]), "r"(b[0]), "r"(b[1]));
}
__device__ __forceinline__ uint32_t f2h2(float lo, float hi) {
    __half2 h = __floats2half2_rn(lo, hi);
    return *(uint32_t*)&h;
}
__device__ __forceinline__ void mma_f16(float* c, const uint32_t* a, const uint32_t* b) {
    asm volatile("mma.sync.aligned.m16n8k16.row.col.f32.f16.f16.f32 "
        "{%0,%1,%2,%3}, {%4,%5,%6,%7}, {%8,%9}, {%0,%1,%2,%3};"
        : "+f"(c[0]), "+f"(c[1]), "+f"(c[2]), "+f"(c[3])
        : "r"(a[0]), "r"(a[1]), "r"(a[2]), "r"(a[3]), "r"(b[0]), "r"(b[1]));
}
__device__ __forceinline__ void cp16(void* s, const void* g, int sz) {
    uint32_t sa = (uint32_t)__cvta_generic_to_shared(s);
    asm volatile("cp.async.cg.shared.global [%0], [%1], 16, %2;" :: "r"(sa), "l"(g), "r"(sz));
}
__device__ __forceinline__ void cp4(void* s, const void* g, int sz) {
    uint32_t sa = (uint32_t)__cvta_generic_to_shared(s);
    asm volatile("cp.async.ca.shared.global [%0], [%1], 4, %2;" :: "r"(sa), "l"(g), "r"(sz));
}
__device__ __forceinline__ void cp_commit() { asm volatile("cp.async.commit_group;"); }
template<int Ng> __device__ __forceinline__ void cp_wait() {
    asm volatile("cp.async.wait_group %0;" :: "n"(Ng));
}

// ---------------- tf32 GEMM: 64x64xBK32, 256 thr (8 warps of 16x32), 3-stage cp.async ----------------
#define GT_BM 64
#define GT_BN 64
#define GT_BK 32
#define GT_SMEM (3 * 2304 * 2 * 4)

template<bool TRANSB, bool BIAS, bool TANH>
__global__ __launch_bounds__(256, 2)
void gemm_tc(const float* __restrict__ A, const float* __restrict__ Bm,
             const float* __restrict__ bias, float* __restrict__ C,
             int M, int N, int K, int lda, int ldb, int ldc,
             long sA, long sB, long sC, float alpha, long sBias)
{
    extern __shared__ float sm[];
    float* As = sm;                     // [3][64][36]
    float* Bs = sm + 3 * 2304;          // [3][32][72] (!T) or [3][64][36] (T)
    const int tid = threadIdx.x;
    const int wid = tid >> 5, lane = tid & 31;
    const int gid = lane >> 2, tig = lane & 3;
    const int m0 = blockIdx.y * GT_BM, n0 = blockIdx.x * GT_BN;
    A  += (long)blockIdx.z * sA;
    Bm += (long)blockIdx.z * sB;
    C  += (long)blockIdx.z * sC;
    if (BIAS) bias += (long)blockIdx.z * sBias;
    const int wm0 = (wid & 3) * 16, wn0 = (wid >> 2) * 32;
    float acc[4][4] = {};

    const int ar = tid >> 2, akc = (tid & 3) * 8;
    const int bkr = tid >> 3, bnc = (tid & 7) * 8;
    const bool a_ok = (m0 + ar) < M;
    const bool b4 = (!TRANSB) && (((ldb & 3) != 0) || ((N & 3) != 0));
    const int nk = (K + GT_BK - 1) / GT_BK;

    auto issueA = [&](int kt, int st) {
        float* dst = As + st * 2304 + ar * 36 + akc;
        const float* src = A + (long)(m0 + ar) * lda + kt * GT_BK + akc;
        #pragma unroll
        for (int q = 0; q < 2; ++q) {
            int sz = (a_ok && (kt * GT_BK + akc + 4 * q) < K) ? 16 : 0;
            cp16(dst + 4 * q, src + 4 * q, sz);
        }
    };
    auto issueB = [&](int kt, int st) {
        if (!TRANSB) {
            float* dst = Bs + st * 2304 + bkr * 72 + bnc;
            const float* src = Bm + (long)(kt * GT_BK + bkr) * ldb + n0 + bnc;
            const bool kok = (kt * GT_BK + bkr) < K;
            if (!b4) {
                #pragma unroll
                for (int q = 0; q < 2; ++q) {
                    int sz = (kok && (n0 + bnc + 4 * q) < N) ? 16 : 0;
                    cp16(dst + 4 * q, src + 4 * q, sz);
                }
            } else {
                #pragma unroll
                for (int e = 0; e < 8; ++e) {
                    int sz = (kok && (n0 + bnc + e) < N) ? 4 : 0;
                    cp4(dst + e, src + e, sz);
                }
            }
        } else {
            float* dst = Bs + st * 2304 + ar * 36 + akc;
            const float* src = Bm + (long)(n0 + ar) * ldb + kt * GT_BK + akc;
            const bool nok = (n0 + ar) < N;
            #pragma unroll
            for (int q = 0; q < 2; ++q) {
                int sz = (nok && (kt * GT_BK + akc + 4 * q) < K) ? 16 : 0;
                cp16(dst + 4 * q, src + 4 * q, sz);
            }
        }
    };

    issueA(0, 0); issueB(0, 0); cp_commit();
    if (nk > 1) { issueA(1, 1); issueB(1, 1); }
    cp_commit();

    int st = 0;
    for (int kt = 0; kt < nk; ++kt) {
        cp_wait<1>();
        __syncthreads();
        const int ktn = kt + 2;
        if (ktn < nk) {
            const int stn = (st + 2 >= 3) ? st - 1 : st + 2;
            issueA(ktn, stn); issueB(ktn, stn);
        }
        cp_commit();
        const float* Ac = As + st * 2304;
        const float* Bc = Bs + st * 2304;
        #pragma unroll
        for (int kk = 0; kk < GT_BK; kk += 8) {
            uint32_t af[4], bf[4][2];
            af[0] = f2tf32(Ac[(wm0 + gid) * 36 + kk + tig]);
            af[1] = f2tf32(Ac[(wm0 + 8 + gid) * 36 + kk + tig]);
            af[2] = f2tf32(Ac[(wm0 + gid) * 36 + kk + tig + 4]);
            af[3] = f2tf32(Ac[(wm0 + 8 + gid) * 36 + kk + tig + 4]);
            #pragma unroll
            for (int nf = 0; nf < 4; ++nf) {
                const int c = wn0 + nf * 8 + gid;
                if (!TRANSB) {
                    bf[nf][0] = f2tf32(Bc[(kk + tig) * 72 + c]);
                    bf[nf][1] = f2tf32(Bc[(kk + tig + 4) * 72 + c]);
                } else {
                    bf[nf][0] = f2tf32(Bc[c * 36 + kk + tig]);
                    bf[nf][1] = f2tf32(Bc[c * 36 + kk + tig + 4]);
                }
            }
            #pragma unroll
            for (int nf = 0; nf < 4; ++nf)
                mma_tf32(acc[nf], af, bf[nf]);
        }
        st = (st + 1 >= 3) ? 0 : st + 1;
    }
    // ---- epilogue ----
    #pragma unroll
    for (int nf = 0; nf < 4; ++nf) {
        const int r = m0 + wm0 + gid;
        const int c = n0 + wn0 + nf * 8 + tig * 2;
        #pragma unroll
        for (int half = 0; half < 2; ++half) {
            const int rr = r + half * 8;
            if (rr >= M) continue;
            #pragma unroll
            for (int j = 0; j < 2; ++j) {
                const int cc = c + j;
                if (cc >= N) continue;
                float v = acc[nf][half * 2 + j] * alpha;
                if (BIAS) v += bias[cc];
                if (TANH) v = tanhf(v);
                C[(long)rr * ldc + cc] = v;
            }
        }
    }
}

// ---------------- W pre-convert: fp32 [49152][768] -> half2-packed [768][32][768] ----------------
__global__ __launch_bounds__(256)
void conv_w_k(const float* __restrict__ W, uint32_t* __restrict__ Whf)
{
    const int t = blockIdx.x;
    const int tid = threadIdx.x;
    const float* Wt = W + (long)t * 64 * 768;
    uint32_t* Dt = Whf + (long)t * 24576;
    #pragma unroll 1
    for (int p = 0; p < 32; ++p) {
        const float* r0 = Wt + (2 * p) * 768;
        const float* r1 = Wt + (2 * p + 1) * 768;
        #pragma unroll
        for (int j = 0; j < 3; ++j) {
            const int c = tid + j * 256;
            Dt[p * 768 + c] = f2h2(r0[c], r1[c]);
        }
    }
}

// ---------------- bilinear: fp16 mma, pre-packed half2 W, 512 thr, 2-step pipeline stages ----------------
#define BL_WSTRIDE 72
#define BL_WSTAGE  (32 * BL_WSTRIDE)        // one t-tile (u32)
#define BL_SMEM    ((2*128*68 + 3*2*BL_WSTAGE) * 4)
__global__ __launch_bounds__(512)
void bilinear_tc(const float* __restrict__ Hs, const float* __restrict__ Ts,
                 const uint32_t* __restrict__ Whf, const float* __restrict__ bias,
                 float* __restrict__ C, int M)
{
    extern __shared__ float sm[];
    float* bh = sm;                      // [128][68]
    float* bt = sm + 128 * 68;           // [128][68]
    uint32_t* Ws = (uint32_t*)(sm + 2 * 128 * 68);   // [3 stages][2 tiles][32][72]
    const int tid = threadIdx.x;
    const int wid = tid >> 5, lane = tid & 31;
    const int gid = lane >> 2, tig = lane & 3;
    const int m0 = blockIdx.y * 128, n0 = blockIdx.x * 64;
    const int wm0 = (wid & 3) * 32, wn0 = (wid >> 2) * 16;   // 16 warps: 4m x 4n
    float acc[2][2][4] = {};
    const int lr = tid >> 2, lc = (tid & 3) * 16;            // HT loads: 128 rows
    const bool lok = (m0 + lr) < M;
    uint32_t btf[2][4][4];
    const int NTP = NBn * 32;            // 384 step-pairs

#define LOADHT(nb_) { \
    const float* hp = Hs + (long)(m0 + lr) * 768 + (nb_) * 64 + lc; \
    const float* tp = Ts + (long)(m0 + lr) * 768 + (nb_) * 64 + lc; \
    _Pragma("unroll") for (int q_ = 0; q_ < 4; ++q_) { \
        float4 hv = lok ? *(const float4*)(hp + 4 * q_) : make_float4(0, 0, 0, 0); \
        float4 tv = lok ? *(const float4*)(tp + 4 * q_) : make_float4(0, 0, 0, 0); \
        *(float4*)&bh[lr * 68 + lc + 4 * q_] = hv; \
        *(float4*)&bt[lr * 68 + lc + 4 * q_] = tv; } }

// load BOTH tiles of a step-pair: threads 0..255, 16 u32 each
#define ISSUEW2(tp_, st_) { \
    if (tid < 256) { \
        const int half_ = tid >> 7, id_ = tid & 127; \
        const int wr_ = id_ >> 2, wq_ = id_ & 3; \
        uint32_t* dst_ = Ws + (st_) * 2 * BL_WSTAGE + half_ * BL_WSTAGE + wr_ * BL_WSTRIDE + wq_ * 16; \
        const uint32_t* src_ = Whf + (long)(2 * (tp_) + half_) * 24576 + wr_ * 768 + n0 + wq_ * 16; \
        cp16(dst_, src_, 16); cp16(dst_ + 4, src_ + 4, 16); \
        cp16(dst_ + 8, src_ + 8, 16); cp16(dst_ + 12, src_ + 12, 16); } }

#define CACHEBT() { \
    _Pragma("unroll") for (int mf_ = 0; mf_ < 2; ++mf_) { const int r0_ = wm0 + mf_ * 16; \
        _Pragma("unroll") for (int j0_ = 0; j0_ < 4; ++j0_) { \
            const int k0_ = j0_ * 16 + tig * 2; \
            btf[mf_][j0_][0] = f2h2(bt[(r0_ + gid) * 68 + k0_],     bt[(r0_ + gid) * 68 + k0_ + 1]); \
            btf[mf_][j0_][1] = f2h2(bt[(r0_ + 8 + gid) * 68 + k0_], bt[(r0_ + 8 + gid) * 68 + k0_ + 1]); \
            btf[mf_][j0_][2] = f2h2(bt[(r0_ + gid) * 68 + k0_ + 8], bt[(r0_ + gid) * 68 + k0_ + 9]); \
            btf[mf_][j0_][3] = f2h2(bt[(r0_ + 8 + gid) * 68 + k0_ + 8], bt[(r0_ + 8 + gid) * 68 + k0_ + 9]); } } }

    LOADHT(0);
    ISSUEW2(0, 0); cp_commit();
    ISSUEW2(1, 1); cp_commit();
    __syncthreads();
    CACHEBT();

    for (int tp = 0; tp < NTP; ++tp) {
        const int st = tp % 3;
        cp_wait<1>();
        __syncthreads();
        if (tp + 2 < NTP) {
            const int stn = (st + 2 >= 3) ? st - 1 : st + 2;
            ISSUEW2(tp + 2, stn);
        }
        cp_commit();
        #pragma unroll
        for (int u = 0; u < 2; ++u) {
            const int t = 2 * tp + u;
            const uint32_t* Wc = Ws + st * 2 * BL_WSTAGE + u * BL_WSTAGE;
            const int i = t & 63;
            float D[2][2][4] = {};
            #pragma unroll
            for (int j0 = 0; j0 < 4; ++j0) {
                uint32_t bfp[2][2];
                #pragma unroll
                for (int nf = 0; nf < 2; ++nf) {
                    const int c = wn0 + nf * 8 + gid;
                    bfp[nf][0] = Wc[(j0 * 8 + tig) * BL_WSTRIDE + c];
                    bfp[nf][1] = Wc[(j0 * 8 + tig + 4) * BL_WSTRIDE + c];
                }
                #pragma unroll
                for (int mf = 0; mf < 2; ++mf)
                    #pragma unroll
                    for (int nf = 0; nf < 2; ++nf)
                        mma_f16(D[mf][nf], btf[mf][j0], bfp[nf]);
            }
            #pragma unroll
            for (int mf = 0; mf < 2; ++mf) {
                const float b0 = bh[(wm0 + mf * 16 + gid) * 68 + i];
                const float b1 = bh[(wm0 + mf * 16 + 8 + gid) * 68 + i];
                #pragma unroll
                for (int nf = 0; nf < 2; ++nf) {
                    acc[mf][nf][0] = fmaf(b0, D[mf][nf][0], acc[mf][nf][0]);
                    acc[mf][nf][1] = fmaf(b0, D[mf][nf][1], acc[mf][nf][1]);
                    acc[mf][nf][2] = fmaf(b1, D[mf][nf][2], acc[mf][nf][2]);
                    acc[mf][nf][3] = fmaf(b1, D[mf][nf][3], acc[mf][nf][3]);
                }
            }
            if (i == 63 && t + 1 < NBn * 64) {
                __syncthreads();
                LOADHT((t + 1) >> 6);
                __syncthreads();
                CACHEBT();
            }
        }
    }
#undef LOADHT
#undef ISSUEW2
#undef CACHEBT
    #pragma unroll
    for (int mf = 0; mf < 2; ++mf) {
        #pragma unroll
        for (int nf = 0; nf < 2; ++nf) {
            const int r = m0 + wm0 + mf * 16 + gid;
            const int c = n0 + wn0 + nf * 8 + tig * 2;
            if (r < M) {
                C[(long)r * 768 + c]     = acc[mf][nf][0] + bias[c];
                C[(long)r * 768 + c + 1] = acc[mf][nf][1] + bias[c + 1];
            }
            if (r + 8 < M) {
                C[(long)(r + 8) * 768 + c]     = acc[mf][nf][2] + bias[c];
                C[(long)(r + 8) * 768 + c + 1] = acc[mf][nf][3] + bias[c + 1];
            }
        }
    }
}

// ---------------- small fused kernels ----------------
__global__ void ent_emb_k(const float* __restrict__ seq, const int* __restrict__ midx,
                          const float* __restrict__ mmask, float* __restrict__ ent_emb)
{
    const int blk = blockIdx.x;
    const int b = blk / (MMn * NEn);
    const int idx = midx[blk];
    const float mask = mmask[blk];
    const float* src = seq + ((long)b * Cn + idx) * Hn;
    float* dst = ent_emb + (long)blk * Hn;
    for (int h = threadIdx.x; h < Hn; h += 256) dst[h] = mask * src[h];
}

__global__ void ent_att_k(const float* __restrict__ att, const int* __restrict__ midx,
                          const float* __restrict__ mmask, float* __restrict__ ent_att)
{
    const int blk = blockIdx.x;
    const int nh = blk % NHn;
    const int e  = (blk / NHn) % NEn;
    const int b  = blk / (NHn * NEn);
    const int c  = threadIdx.x;
    const int* mi = midx + (b * NEn + e) * MMn;
    const float* mk = mmask + (b * NEn + e) * MMn;
    float cnt = 0.f, s = 0.f;
    for (int m = 0; m < MMn; ++m) {
        const float w = mk[m];
        cnt += w;
        s += w * att[(((long)b * NHn + nh) * Cn + mi[m]) * Cn + c];
    }
    ent_att[(long)blk * Cn + c] = s / cnt;
}

__global__ void ht_att_k(const float* __restrict__ ent_att, const int* __restrict__ hts,
                         float* __restrict__ ht_att)
{
    const int bp = blockIdx.x;
    const int b = bp / Pn;
    const int hi = hts[bp * 2], ti = hts[bp * 2 + 1];
    const int c = threadIdx.x;
    const float* ha = ent_att + (long)(b * NEn + hi) * NHn * Cn;
    const float* ta = ent_att + (long)(b * NEn + ti) * NHn * Cn;
    float v = 0.f;
    #pragma unroll
    for (int nh = 0; nh < NHn; ++nh) v += ha[nh * Cn + c] * ta[nh * Cn + c];
    v *= (1.f / 12.f);
    __shared__ float red[512];
    red[c] = v; __syncthreads();
    for (int s = 256; s > 0; s >>= 1) { if (c < s) red[c] += red[c + s]; __syncthreads(); }
    ht_att[(long)bp * Cn + c] = v / (red[0] + 1e-5f);
}

__global__ void pool_attn_k(const float* __restrict__ htq, const float* __restrict__ ent_q,
                            const float* __restrict__ ent_emb, const float* __restrict__ mmask,
                            const int* __restrict__ hts, float* __restrict__ hs_att,
                            float* __restrict__ ts_att)
{
    const int bp = blockIdx.x;
    const int side = blockIdx.y;
    const int b = bp / Pn;
    const int e = hts[bp * 2 + side];
    __shared__ float qs[QSn];
    __shared__ float gs[MMn];
    const int tid = threadIdx.x;
    if (tid < QSn) qs[tid] = htq[(long)bp * QSn + tid];
    __syncthreads();
    if (tid < MMn) {
        const float* eq = ent_q + ((long)(b * NEn + e) * MMn + tid) * QSn;
        float d = 0.f;
        for (int i = 0; i < QSn; ++i) d += qs[i] * eq[i];
        const float mk = mmask[(b * NEn + e) * MMn + tid];
        gs[tid] = (mk > 0.f) ? d * SCALE_EMB : kNEG;
    }
    __syncthreads();
    float mx = -1e30f;
    for (int m = 0; m < MMn; ++m) mx = fmaxf(mx, gs[m]);
    float w[MMn]; float ssum = 0.f;
    for (int m = 0; m < MMn; ++m) { w[m] = expf(gs[m] - mx); ssum += w[m]; }
    const float inv = 1.f / ssum;
    const float* emb = ent_emb + (long)(b * NEn + e) * MMn * Hn;
    float* out = (side ? ts_att : hs_att) + (long)bp * Hn;
    for (int h = tid; h < Hn; h += 256) {
        float acc2 = 0.f;
        for (int m = 0; m < MMn; ++m) acc2 += w[m] * emb[m * Hn + h];
        out[h] = acc2 * inv;
    }
}

__global__ void cat2_k(const float* __restrict__ hs_att, const float* __restrict__ ts_att,
                       const float* __restrict__ rs, float* __restrict__ cat_h,
                       float* __restrict__ cat_t)
{
    const long r = blockIdx.x;
    for (int h = threadIdx.x; h < Hn; h += 256) {
        const float rv = rs[r * Hn + h];
        cat_h[r * 1536 + h]       = hs_att[r * Hn + h];
        cat_h[r * 1536 + 768 + h] = rv;
        cat_t[r * 1536 + h]       = ts_att[r * Hn + h];
        cat_t[r * 1536 + 768 + h] = rv;
    }
}

__global__ void catpp_k(const float* __restrict__ pairg, const float* __restrict__ pos_emb,
                        const int* __restrict__ hts, float* __restrict__ catpp)
{
    const long r = blockIdx.x;
    const int hi = hts[r * 2], ti = hts[r * 2 + 1];
    if (threadIdx.x < POSn) {
        catpp[r * 1024 + threadIdx.x]       = pos_emb[hi * POSn + threadIdx.x];
        catpp[r * 1024 + 896 + threadIdx.x] = pos_emb[ti * POSn + threadIdx.x];
    }
    for (int h = threadIdx.x; h < Hn; h += 256)
        catpp[r * 1024 + 128 + h] = pairg[r * Hn + h];
}

__global__ void pair_softmax_k(float* __restrict__ sc, const float* __restrict__ vis)
{
    const long bp = blockIdx.x;
    float* row = sc + bp * Pn;
    const float* vr = vis + bp * Pn;
    const int tid = threadIdx.x;
    __shared__ float red[128];
    float mx = -1e30f;
    for (int q = tid; q < Pn; q += 128) {
        const float v = (vr[q] > 0.f) ? row[q] : kNEG;
        mx = fmaxf(mx, v);
    }
    red[tid] = mx; __syncthreads();
    for (int s = 64; s > 0; s >>= 1) { if (tid < s) red[tid] = fmaxf(red[tid], red[tid + s]); __syncthreads(); }
    mx = red[0]; __syncthreads();
    float sum = 0.f;
    for (int q = tid; q < Pn; q += 128) {
        const float v = (vr[q] > 0.f) ? row[q] : kNEG;
        sum += expf(v - mx);
    }
    red[tid] = sum; __syncthreads();
    for (int s = 64; s > 0; s >>= 1) { if (tid < s) red[tid] += red[tid + s]; __syncthreads(); }
    const float inv = 1.f / red[0];
    for (int q = tid; q < Pn; q += 128) {
        const float v = (vr[q] > 0.f) ? row[q] : kNEG;
        row[q] = expf(v - mx) * inv;
    }
}

__global__ void catfeat_k(const float* __restrict__ hs, const float* __restrict__ ts,
                          const float* __restrict__ pair1, const float* __restrict__ atto,
                          float* __restrict__ catf)
{
    const long r = blockIdx.x;
    for (int h = threadIdx.x; h < Hn; h += 256) {
        catf[r * 2304 + h]        = hs[r * Hn + h];
        catf[r * 2304 + 768 + h]  = ts[r * Hn + h];
        catf[r * 2304 + 1536 + h] = pair1[r * Hn + h] + atto[r * Hn + h];
    }
}

// ---------------- launcher ----------------
extern "C" void kernel_launch(void* const* d_in, const int* in_sizes, int n_in,
                              void* d_out, int out_size)
{
    (void)in_sizes; (void)n_in; (void)out_size;
    const float* seq   = (const float*)d_in[0];
    const float* att   = (const float*)d_in[1];
    const int*   midx  = (const int*)  d_in[2];
    const float* mmask = (const float*)d_in[3];
    const int*   hts   = (const int*)  d_in[4];
    const float* vis   = (const float*)d_in[5];
    const float* Wcq = (const float*)d_in[6],  *bcq = (const float*)d_in[7];
    const float* Weq = (const float*)d_in[8],  *beq = (const float*)d_in[9];
    const float* Whe = (const float*)d_in[10], *bhe = (const float*)d_in[11];
    const float* Wte = (const float*)d_in[12], *bte = (const float*)d_in[13];
    const float* Wbl = (const float*)d_in[14], *bbl = (const float*)d_in[15];
    const float* Wpp = (const float*)d_in[16], *bpp = (const float*)d_in[17];
    const float* Wgq = (const float*)d_in[18];
    const float* Wgk = (const float*)d_in[19];
    const float* Wgv = (const float*)d_in[20];
    const float* Wp1 = (const float*)d_in[21], *bp1 = (const float*)d_in[22];
    const float* Wp2 = (const float*)d_in[23], *bp2 = (const float*)d_in[24];
    const float* pos = (const float*)d_in[25];
    float* out = (float*)d_out;

    float* base = nullptr;
    cudaGetSymbolAddress((void**)&base, g_scratch);
    float* ent_emb = base + OFF_ENT_EMB;
    float* ent_att = base + OFF_ENT_ATT;
    float* ent_q   = base + OFF_ENT_Q;
    float* ht_att  = base + OFF_HT_ATT;
    float* rs      = base + OFF_RS;
    float* htqb    = base + OFF_HTQ;
    float* hs_att  = base + OFF_HS_ATT;
    float* ts_att  = base + OFF_TS_ATT;
    float* cat_h   = base + OFF_CAT_H;
    float* hs_t    = base + OFF_HS;
    float* ts_t    = base + OFF_TS;
    float* pairg   = base + OFF_PAIRG;
    float* catpp   = base + OFF_CATPP;
    float* pair1   = base + OFF_PAIR1;
    float* qb      = base + OFF_QB;
    float* kb      = base + OFF_KB;
    float* vb      = base + OFF_VB;
    float* scb     = base + OFF_SC;
    float* atto    = base + OFF_ATTO;
    float* catf    = base + OFF_CATF;
    float* h1      = base + OFF_H1;
    float* wcat    = base + OFF_WCAT;
    float* wqkv    = base + OFF_WQKV;
    float* wb      = base + OFF_WB;
    uint32_t* whf  = (uint32_t*)(base + OFF_WHF);

    cudaFuncSetAttribute(gemm_tc<false,false,false>, cudaFuncAttributeMaxDynamicSharedMemorySize, GT_SMEM);
    cudaFuncSetAttribute(gemm_tc<false,true,false>,  cudaFuncAttributeMaxDynamicSharedMemorySize, GT_SMEM);
    cudaFuncSetAttribute(gemm_tc<false,true,true>,   cudaFuncAttributeMaxDynamicSharedMemorySize, GT_SMEM);
    cudaFuncSetAttribute(gemm_tc<true,false,false>,  cudaFuncAttributeMaxDynamicSharedMemorySize, GT_SMEM);
    cudaFuncSetAttribute(bilinear_tc, cudaFuncAttributeMaxDynamicSharedMemorySize, BL_SMEM);

    // 0) pack batched weights/biases; pre-convert bilinear W to half2 layout
    cudaMemcpyAsync(wcat,              Whe, 1536UL*768*4, cudaMemcpyDeviceToDevice);
    cudaMemcpyAsync(wcat + 1536UL*768, Wte, 1536UL*768*4, cudaMemcpyDeviceToDevice);
    cudaMemcpyAsync(wqkv,              Wgq, 768UL*768*4,  cudaMemcpyDeviceToDevice);
    cudaMemcpyAsync(wqkv + 768UL*768,  Wgk, 768UL*768*4,  cudaMemcpyDeviceToDevice);
    cudaMemcpyAsync(wqkv + 2UL*768*768,Wgv, 768UL*768*4,  cudaMemcpyDeviceToDevice);
    cudaMemcpyAsync(wb,                bhe, 768UL*4,      cudaMemcpyDeviceToDevice);
    cudaMemcpyAsync(wb + 768,          bte, 768UL*4,      cudaMemcpyDeviceToDevice);
    conv_w_k<<<768, 256>>>(Wbl, whf);

    // 1) entity gathers
    ent_emb_k<<<Bn * NEn * MMn, 256>>>(seq, midx, mmask, ent_emb);
    ent_att_k<<<Bn * NEn * NHn, 512>>>(att, midx, mmask, ent_att);
    // 2) pair context attention
    ht_att_k<<<BPn, 512>>>(ent_att, hts, ht_att);
    // 3) rs = ht_att @ seq (batched)
    gemm_tc<false,false,false><<<dim3(12, 6, 4), 256, GT_SMEM>>>(ht_att, seq, nullptr, rs,
        Pn, Hn, Cn, Cn, Hn, Hn, 380L*512, 512L*768, 380L*768, 1.f, 0L);
    // 4) htq, ent_q
    gemm_tc<false,true,false><<<dim3(2, 24, 1), 256, GT_SMEM>>>(rs, Wcq, bcq, htqb,
        BPn, QSn, Hn, Hn, QSn, QSn, 0, 0, 0, 1.f, 0L);
    gemm_tc<false,true,false><<<dim3(2, 29, 1), 256, GT_SMEM>>>(ent_emb, Weq, beq, ent_q,
        1840, QSn, Hn, Hn, QSn, QSn, 0, 0, 0, 1.f, 0L);
    // 5) mention-pool softmax
    pool_attn_k<<<dim3(BPn, 2), 256>>>(htqb, ent_q, ent_emb, mmask, hts, hs_att, ts_att);
    // 6) hs/ts projections — ONE z=2 batched launch (per-z bias)
    cat2_k<<<BPn, 256>>>(hs_att, ts_att, rs, cat_h, base + OFF_CAT_T);
    gemm_tc<false,true,true><<<dim3(12, 24, 2), 256, GT_SMEM>>>(cat_h, wcat, wb, hs_t,
        BPn, EMBn, 1536, 1536, EMBn, EMBn, 1520L*1536, 1536L*768, 1520L*768, 1.f, 768L);
    // 7) grouped bilinear (fp16 mma, pre-packed W, paired pipeline stages)
    bilinear_tc<<<dim3(12, 12), 512, BL_SMEM>>>(hs_t, ts_t, whf, bbl, pairg, BPn);
    // 8) pos concat + Wpp
    catpp_k<<<BPn, 256>>>(pairg, pos, hts, catpp);
    gemm_tc<false,true,true><<<dim3(12, 24, 1), 256, GT_SMEM>>>(catpp, Wpp, bpp, pair1,
        BPn, EMBn, 1024, 1024, EMBn, EMBn, 0, 0, 0, 1.f, 0L);
    // 9) pair-graph attention: q/k/v in ONE batched launch (z=3)
    gemm_tc<false,false,false><<<dim3(12, 24, 3), 256, GT_SMEM>>>(pair1, wqkv, nullptr, qb,
        BPn, EMBn, EMBn, EMBn, EMBn, EMBn, 0, 768L*768, 1520L*768, 1.f, 0L);
    gemm_tc<true,false,false><<<dim3(6, 6, 4), 256, GT_SMEM>>>(qb, kb, nullptr, scb,
        Pn, Pn, EMBn, EMBn, EMBn, Pn, 380L*768, 380L*768, 380L*380, SCALE_EMB, 0L);
    pair_softmax_k<<<BPn, 128>>>(scb, vis);
    gemm_tc<false,false,false><<<dim3(12, 6, 4), 256, GT_SMEM>>>(scb, vb, nullptr, atto,
        Pn, EMBn, Pn, Pn, EMBn, EMBn, 380L*380, 380L*768, 380L*768, 1.f, 0L);
    // 10) classifier head
    catfeat_k<<<BPn, 256>>>(hs_t, ts_t, pair1, atto, catf);
    gemm_tc<false,true,true><<<dim3(12, 24, 1), 256, GT_SMEM>>>(catf, Wp1, bp1, h1,
        BPn, EMBn, 2304, 2304, EMBn, EMBn, 0, 0, 0, 1.f, 0L);
    gemm_tc<false,true,false><<<dim3(2, 24, 1), 256, GT_SMEM>>>(h1, Wp2, bp2, out,
        BPn, NCLSn, EMBn, EMBn, NCLSn, NCLSn, 0, 0, 0, 1.f, 0L);
}

// round 16
// speedup vs baseline: 1.1802x; 1.0697x over previous
#include <cuda_runtime.h>
#include <cuda_fp16.h>
#include <stdint.h>
#include <math.h>

// ---------------- problem constants ----------------
#define Bn   4
#define Cn   512
#define Hn   768
#define NHn  12
#define NEn  20
#define MMn  23
#define Pn   380
#define BPn  1520
#define QSn  128
#define EMBn 768
#define NBn  12
#define BLKn 64
#define NCLSn 97
#define POSn 128

static __device__ __constant__ float kNEG = -10000.0f;
#define SCALE_EMB 0.03608439182435161f   // 1/sqrt(768)

// ---------------- scratch ----------------
#define OFF_ENT_EMB 0UL
#define OFF_ENT_ATT (OFF_ENT_EMB + 1840UL*768)
#define OFF_ENT_Q   (OFF_ENT_ATT + 960UL*512)
#define OFF_HT_ATT  (OFF_ENT_Q   + 1840UL*128)
#define OFF_RS      (OFF_HT_ATT  + 1520UL*512)
#define OFF_HTQ     (OFF_RS      + 1520UL*768)
#define OFF_HS_ATT  (OFF_HTQ     + 1520UL*128)
#define OFF_TS_ATT  (OFF_HS_ATT  + 1520UL*768)
#define OFF_CAT_H   (OFF_TS_ATT  + 1520UL*768)
#define OFF_CAT_T   (OFF_CAT_H   + 1520UL*1536)
#define OFF_HS      (OFF_CAT_T   + 1520UL*1536)
#define OFF_TS      (OFF_HS      + 1520UL*768)
#define OFF_PAIRG   (OFF_TS      + 1520UL*768)
#define OFF_CATPP   (OFF_PAIRG   + 1520UL*768)
#define OFF_PAIR1   (OFF_CATPP   + 1520UL*1024)
#define OFF_QB      (OFF_PAIR1   + 1520UL*768)
#define OFF_KB      (OFF_QB      + 1520UL*768)
#define OFF_VB      (OFF_KB      + 1520UL*768)
#define OFF_SC      (OFF_VB      + 1520UL*768)
#define OFF_ATTO    (OFF_SC      + 4UL*380*380)
#define OFF_CATF    (OFF_ATTO    + 1520UL*768)
#define OFF_H1      (OFF_CATF    + 1520UL*2304)
#define OFF_WB      (OFF_H1      + 1520UL*768)
#define OFF_WHF     (OFF_WB      + 2UL*768)              // 768*24576 u32 (bilinear W)
#define OFF_WCQP    (OFF_WHF     + 768UL*24576)          // 384*128 u32
#define OFF_WEQP    (OFF_WCQP    + 384UL*128)
#define OFF_WCATP   (OFF_WEQP    + 384UL*128)            // 2 * 768*768 u32
#define OFF_WPPP    (OFF_WCATP   + 2UL*768*768)          // 512*768
#define OFF_WQKVP   (OFF_WPPP    + 512UL*768)            // 3 * 384*768
#define OFF_WP1P    (OFF_WQKVP   + 3UL*384*768)          // 1152*768
#define SCRATCH_TOTAL (OFF_WP1P  + 1152UL*768)

__device__ float g_scratch[SCRATCH_TOTAL];

// ---------------- helpers ----------------
__device__ __forceinline__ uint32_t f2tf32(float x) {
    uint32_t r; asm("cvt.rna.tf32.f32 %0, %1;" : "=r"(r) : "f"(x)); return r;
}
__device__ __forceinline__ void mma_tf32(float* c, const uint32_t* a, const uint32_t* b) {
    asm volatile("mma.sync.aligned.m16n8k8.row.col.f32.tf32.tf32.f32 "
        "{%0,%1,%2,%3}, {%4,%5,%6,%7}, {%8,%9}, {%0,%1,%2,%3};"
        : "+f"(c[0]), "+f"(c[1]), "+f"(c[2]), "+f"(c[3])
        : "r"(a[0]), "r"(a[1]), "r"(a[2]), "r"(a[3]), "r"(b[0]), "r"(b[1]));
}
__device__ __forceinline__ uint32_t f2h2(float lo, float hi) {
    __half2 h = __floats2half2_rn(lo, hi);
    return *(uint32_t*)&h;
}
__device__ __forceinline__ void mma_f16(float* c, const uint32_t* a, const uint32_t* b) {
    asm volatile("mma.sync.aligned.m16n8k16.row.col.f32.f16.f16.f32 "
        "{%0,%1,%2,%3}, {%4,%5,%6,%7}, {%8,%9}, {%0,%1,%2,%3};"
        : "+f"(c[0]), "+f"(c[1]), "+f"(c[2]), "+f"(c[3])
        : "r"(a[0]), "r"(a[1]), "r"(a[2]), "r"(a[3]), "r"(b[0]), "r"(b[1]));
}
__device__ __forceinline__ void cp16(void* s, const void* g, int sz) {
    uint32_t sa = (uint32_t)__cvta_generic_to_shared(s);
    asm volatile("cp.async.cg.shared.global [%0], [%1], 16, %2;" :: "r"(sa), "l"(g), "r"(sz));
}
__device__ __forceinline__ void cp4(void* s, const void* g, int sz) {
    uint32_t sa = (uint32_t)__cvta_generic_to_shared(s);
    asm volatile("cp.async.ca.shared.global [%0], [%1], 4, %2;" :: "r"(sa), "l"(g), "r"(sz));
}
__device__ __forceinline__ void cp_commit() { asm volatile("cp.async.commit_group;"); }
template<int Ng> __device__ __forceinline__ void cp_wait() {
    asm volatile("cp.async.wait_group %0;" :: "n"(Ng));
}

// ---------------- tf32 GEMM (dynamic B): 64x64xBK32, 256 thr, 3-stage cp.async ----------------
#define GT_BM 64
#define GT_BN 64
#define GT_BK 32
#define GT_SMEM (3 * 2304 * 2 * 4)

template<bool TRANSB, bool BIAS, bool TANH>
__global__ __launch_bounds__(256, 2)
void gemm_tc(const float* __restrict__ A, const float* __restrict__ Bm,
             const float* __restrict__ bias, float* __restrict__ C,
             int M, int N, int K, int lda, int ldb, int ldc,
             long sA, long sB, long sC, float alpha, long sBias)
{
    extern __shared__ float sm[];
    float* As = sm;                     // [3][64][36]
    float* Bs = sm + 3 * 2304;          // [3][32][72] (!T) or [3][64][36] (T)
    const int tid = threadIdx.x;
    const int wid = tid >> 5, lane = tid & 31;
    const int gid = lane >> 2, tig = lane & 3;
    const int m0 = blockIdx.y * GT_BM, n0 = blockIdx.x * GT_BN;
    A  += (long)blockIdx.z * sA;
    Bm += (long)blockIdx.z * sB;
    C  += (long)blockIdx.z * sC;
    if (BIAS) bias += (long)blockIdx.z * sBias;
    const int wm0 = (wid & 3) * 16, wn0 = (wid >> 2) * 32;
    float acc[4][4] = {};

    const int ar = tid >> 2, akc = (tid & 3) * 8;
    const int bkr = tid >> 3, bnc = (tid & 7) * 8;
    const bool a_ok = (m0 + ar) < M;
    const bool b4 = (!TRANSB) && (((ldb & 3) != 0) || ((N & 3) != 0));
    const int nk = (K + GT_BK - 1) / GT_BK;

    auto issueA = [&](int kt, int st) {
        float* dst = As + st * 2304 + ar * 36 + akc;
        const float* src = A + (long)(m0 + ar) * lda + kt * GT_BK + akc;
        #pragma unroll
        for (int q = 0; q < 2; ++q) {
            int sz = (a_ok && (kt * GT_BK + akc + 4 * q) < K) ? 16 : 0;
            cp16(dst + 4 * q, src + 4 * q, sz);
        }
    };
    auto issueB = [&](int kt, int st) {
        if (!TRANSB) {
            float* dst = Bs + st * 2304 + bkr * 72 + bnc;
            const float* src = Bm + (long)(kt * GT_BK + bkr) * ldb + n0 + bnc;
            const bool kok = (kt * GT_BK + bkr) < K;
            if (!b4) {
                #pragma unroll
                for (int q = 0; q < 2; ++q) {
                    int sz = (kok && (n0 + bnc + 4 * q) < N) ? 16 : 0;
                    cp16(dst + 4 * q, src + 4 * q, sz);
                }
            } else {
                #pragma unroll
                for (int e = 0; e < 8; ++e) {
                    int sz = (kok && (n0 + bnc + e) < N) ? 4 : 0;
                    cp4(dst + e, src + e, sz);
                }
            }
        } else {
            float* dst = Bs + st * 2304 + ar * 36 + akc;
            const float* src = Bm + (long)(n0 + ar) * ldb + kt * GT_BK + akc;
            const bool nok = (n0 + ar) < N;
            #pragma unroll
            for (int q = 0; q < 2; ++q) {
                int sz = (nok && (kt * GT_BK + akc + 4 * q) < K) ? 16 : 0;
                cp16(dst + 4 * q, src + 4 * q, sz);
            }
        }
    };

    issueA(0, 0); issueB(0, 0); cp_commit();
    if (nk > 1) { issueA(1, 1); issueB(1, 1); }
    cp_commit();

    int st = 0;
    for (int kt = 0; kt < nk; ++kt) {
        cp_wait<1>();
        __syncthreads();
        const int ktn = kt + 2;
        if (ktn < nk) {
            const int stn = (st + 2 >= 3) ? st - 1 : st + 2;
            issueA(ktn, stn); issueB(ktn, stn);
        }
        cp_commit();
        const float* Ac = As + st * 2304;
        const float* Bc = Bs + st * 2304;
        #pragma unroll
        for (int kk = 0; kk < GT_BK; kk += 8) {
            uint32_t af[4], bf[4][2];
            af[0] = f2tf32(Ac[(wm0 + gid) * 36 + kk + tig]);
            af[1] = f2tf32(Ac[(wm0 + 8 + gid) * 36 + kk + tig]);
            af[2] = f2tf32(Ac[(wm0 + gid) * 36 + kk + tig + 4]);
            af[3] = f2tf32(Ac[(wm0 + 8 + gid) * 36 + kk + tig + 4]);
            #pragma unroll
            for (int nf = 0; nf < 4; ++nf) {
                const int c = wn0 + nf * 8 + gid;
                if (!TRANSB) {
                    bf[nf][0] = f2tf32(Bc[(kk + tig) * 72 + c]);
                    bf[nf][1] = f2tf32(Bc[(kk + tig + 4) * 72 + c]);
                } else {
                    bf[nf][0] = f2tf32(Bc[c * 36 + kk + tig]);
                    bf[nf][1] = f2tf32(Bc[c * 36 + kk + tig + 4]);
                }
            }
            #pragma unroll
            for (int nf = 0; nf < 4; ++nf)
                mma_tf32(acc[nf], af, bf[nf]);
        }
        st = (st + 1 >= 3) ? 0 : st + 1;
    }
    #pragma unroll
    for (int nf = 0; nf < 4; ++nf) {
        const int r = m0 + wm0 + gid;
        const int c = n0 + wn0 + nf * 8 + tig * 2;
        #pragma unroll
        for (int half = 0; half < 2; ++half) {
            const int rr = r + half * 8;
            if (rr >= M) continue;
            #pragma unroll
            for (int j = 0; j < 2; ++j) {
                const int cc = c + j;
                if (cc >= N) continue;
                float v = acc[nf][half * 2 + j] * alpha;
                if (BIAS) v += bias[cc];
                if (TANH) v = tanhf(v);
                C[(long)rr * ldc + cc] = v;
            }
        }
    }
}

// ---------------- fp16 GEMM with PRE-PACKED half2 B: 64x64xBK32, 256 thr ----------------
// Bp: [K/2][N] u32, Bp[p][c] = half2(B[2p][c], B[2p+1][c]). Requires K%32==0, N%64==0.
#define GF_SMEM ((3 * 2304 + 3 * 1152) * 4)

template<bool BIAS, bool TANH>
__global__ __launch_bounds__(256, 2)
void gemm_f16w(const float* __restrict__ A, const uint32_t* __restrict__ Bp,
               const float* __restrict__ bias, float* __restrict__ C,
               int M, int N, int K, int lda, int ldc,
               long sA, long sB, long sC, long sBias)
{
    extern __shared__ float sm[];
    float* As = sm;                             // [3][64][36]
    uint32_t* Bsp = (uint32_t*)(sm + 3 * 2304); // [3][16][72]
    const int tid = threadIdx.x;
    const int wid = tid >> 5, lane = tid & 31;
    const int gid = lane >> 2, tig = lane & 3;
    const int m0 = blockIdx.y * GT_BM, n0 = blockIdx.x * GT_BN;
    A  += (long)blockIdx.z * sA;
    Bp += (long)blockIdx.z * sB;
    C  += (long)blockIdx.z * sC;
    if (BIAS) bias += (long)blockIdx.z * sBias;
    const int wm0 = (wid & 3) * 16, wn0 = (wid >> 2) * 32;
    float acc[4][4] = {};

    const int ar = tid >> 2, akc = (tid & 3) * 8;
    const int bkr = tid >> 4, bnc = (tid & 15) * 4;     // 16 pair-rows x 64 u32
    const bool a_ok = (m0 + ar) < M;
    const int nk = K / GT_BK;

    auto issueA = [&](int kt, int st) {
        float* dst = As + st * 2304 + ar * 36 + akc;
        const float* src = A + (long)(m0 + ar) * lda + kt * GT_BK + akc;
        #pragma unroll
        for (int q = 0; q < 2; ++q) {
            int sz = a_ok ? 16 : 0;
            cp16(dst + 4 * q, src + 4 * q, sz);
        }
    };
    auto issueB = [&](int kt, int st) {
        uint32_t* dst = Bsp + st * 1152 + bkr * 72 + bnc;
        const uint32_t* src = Bp + (long)(kt * 16 + bkr) * N + n0 + bnc;
        cp16(dst, src, 16);
    };

    issueA(0, 0); issueB(0, 0); cp_commit();
    if (nk > 1) { issueA(1, 1); issueB(1, 1); }
    cp_commit();

    int st = 0;
    for (int kt = 0; kt < nk; ++kt) {
        cp_wait<1>();
        __syncthreads();
        const int ktn = kt + 2;
        if (ktn < nk) {
            const int stn = (st + 2 >= 3) ? st - 1 : st + 2;
            issueA(ktn, stn); issueB(ktn, stn);
        }
        cp_commit();
        const float* Ac = As + st * 2304;
        const uint32_t* Bc = Bsp + st * 1152;
        #pragma unroll
        for (int kk = 0; kk < GT_BK; kk += 16) {
            const int k0 = kk + tig * 2;
            const int pb = (kk >> 1) + tig;          // pair-row base
            uint32_t af[4], bf[4][2];
            {
                const float* r0 = Ac + (wm0 + gid) * 36;
                const float* r1 = Ac + (wm0 + 8 + gid) * 36;
                af[0] = f2h2(r0[k0], r0[k0 + 1]);
                af[1] = f2h2(r1[k0], r1[k0 + 1]);
                af[2] = f2h2(r0[k0 + 8], r0[k0 + 9]);
                af[3] = f2h2(r1[k0 + 8], r1[k0 + 9]);
            }
            #pragma unroll
            for (int nf = 0; nf < 4; ++nf) {
                const int c = wn0 + nf * 8 + gid;
                bf[nf][0] = Bc[pb * 72 + c];
                bf[nf][1] = Bc[(pb + 4) * 72 + c];
            }
            #pragma unroll
            for (int nf = 0; nf < 4; ++nf)
                mma_f16(acc[nf], af, bf[nf]);
        }
        st = (st + 1 >= 3) ? 0 : st + 1;
    }
    #pragma unroll
    for (int nf = 0; nf < 4; ++nf) {
        const int r = m0 + wm0 + gid;
        const int c = n0 + wn0 + nf * 8 + tig * 2;
        #pragma unroll
        for (int half = 0; half < 2; ++half) {
            const int rr = r + half * 8;
            if (rr >= M) continue;
            #pragma unroll
            for (int j = 0; j < 2; ++j) {
                const int cc = c + j;
                if (cc >= N) continue;
                float v = acc[nf][half * 2 + j];
                if (BIAS) v += bias[cc];
                if (TANH) v = tanhf(v);
                C[(long)rr * ldc + cc] = v;
            }
        }
    }
}

// ---------------- generic weight pack: fp32 [K][N] -> u32 [K/2][N] half2 ----------------
__global__ __launch_bounds__(256)
void pack_w_k(const float* __restrict__ W, uint32_t* __restrict__ out, int N)
{
    const int p = blockIdx.x;
    const float* r0 = W + (long)(2 * p) * N;
    const float* r1 = r0 + N;
    for (int c = threadIdx.x; c < N; c += 256)
        out[(long)p * N + c] = f2h2(r0[c], r1[c]);
}

// ---------------- bilinear W pre-convert: fp32 [49152][768] -> half2 [768][32][768] ----------------
__global__ __launch_bounds__(256)
void conv_w_k(const float* __restrict__ W, uint32_t* __restrict__ Whf)
{
    const int t = blockIdx.x;
    const int tid = threadIdx.x;
    const float* Wt = W + (long)t * 64 * 768;
    uint32_t* Dt = Whf + (long)t * 24576;
    #pragma unroll 1
    for (int p = 0; p < 32; ++p) {
        const float* r0 = Wt + (2 * p) * 768;
        const float* r1 = Wt + (2 * p + 1) * 768;
        #pragma unroll
        for (int j = 0; j < 3; ++j) {
            const int c = tid + j * 256;
            Dt[p * 768 + c] = f2h2(r0[c], r1[c]);
        }
    }
}

// ---------------- bilinear: fp16 mma, pre-packed half2 W, 512 thr, 2-step pipeline stages ----------------
#define BL_WSTRIDE 72
#define BL_WSTAGE  (32 * BL_WSTRIDE)
#define BL_SMEM    ((2*128*68 + 3*2*BL_WSTAGE) * 4)
__global__ __launch_bounds__(512)
void bilinear_tc(const float* __restrict__ Hs, const float* __restrict__ Ts,
                 const uint32_t* __restrict__ Whf, const float* __restrict__ bias,
                 float* __restrict__ C, int M)
{
    extern __shared__ float sm[];
    float* bh = sm;
    float* bt = sm + 128 * 68;
    uint32_t* Ws = (uint32_t*)(sm + 2 * 128 * 68);   // [3 stages][2 tiles][32][72]
    const int tid = threadIdx.x;
    const int wid = tid >> 5, lane = tid & 31;
    const int gid = lane >> 2, tig = lane & 3;
    const int m0 = blockIdx.y * 128, n0 = blockIdx.x * 64;
    const int wm0 = (wid & 3) * 32, wn0 = (wid >> 2) * 16;
    float acc[2][2][4] = {};
    const int lr = tid >> 2, lc = (tid & 3) * 16;
    const bool lok = (m0 + lr) < M;
    uint32_t btf[2][4][4];
    const int NTP = NBn * 32;

#define LOADHT(nb_) { \
    const float* hp = Hs + (long)(m0 + lr) * 768 + (nb_) * 64 + lc; \
    const float* tp = Ts + (long)(m0 + lr) * 768 + (nb_) * 64 + lc; \
    _Pragma("unroll") for (int q_ = 0; q_ < 4; ++q_) { \
        float4 hv = lok ? *(const float4*)(hp + 4 * q_) : make_float4(0, 0, 0, 0); \
        float4 tv = lok ? *(const float4*)(tp + 4 * q_) : make_float4(0, 0, 0, 0); \
        *(float4*)&bh[lr * 68 + lc + 4 * q_] = hv; \
        *(float4*)&bt[lr * 68 + lc + 4 * q_] = tv; } }

#define ISSUEW2(tp_, st_) { \
    if (tid < 256) { \
        const int half_ = tid >> 7, id_ = tid & 127; \
        const int wr_ = id_ >> 2, wq_ = id_ & 3; \
        uint32_t* dst_ = Ws + (st_) * 2 * BL_WSTAGE + half_ * BL_WSTAGE + wr_ * BL_WSTRIDE + wq_ * 16; \
        const uint32_t* src_ = Whf + (long)(2 * (tp_) + half_) * 24576 + wr_ * 768 + n0 + wq_ * 16; \
        cp16(dst_, src_, 16); cp16(dst_ + 4, src_ + 4, 16); \
        cp16(dst_ + 8, src_ + 8, 16); cp16(dst_ + 12, src_ + 12, 16); } }

#define CACHEBT() { \
    _Pragma("unroll") for (int mf_ = 0; mf_ < 2; ++mf_) { const int r0_ = wm0 + mf_ * 16; \
        _Pragma("unroll") for (int j0_ = 0; j0_ < 4; ++j0_) { \
            const int k0_ = j0_ * 16 + tig * 2; \
            btf[mf_][j0_][0] = f2h2(bt[(r0_ + gid) * 68 + k0_],     bt[(r0_ + gid) * 68 + k0_ + 1]); \
            btf[mf_][j0_][1] = f2h2(bt[(r0_ + 8 + gid) * 68 + k0_], bt[(r0_ + 8 + gid) * 68 + k0_ + 1]); \
            btf[mf_][j0_][2] = f2h2(bt[(r0_ + gid) * 68 + k0_ + 8], bt[(r0_ + gid) * 68 + k0_ + 9]); \
            btf[mf_][j0_][3] = f2h2(bt[(r0_ + 8 + gid) * 68 + k0_ + 8], bt[(r0_ + 8 + gid) * 68 + k0_ + 9]); } } }

    LOADHT(0);
    ISSUEW2(0, 0); cp_commit();
    ISSUEW2(1, 1); cp_commit();
    __syncthreads();
    CACHEBT();

    for (int tp = 0; tp < NTP; ++tp) {
        const int st = tp % 3;
        cp_wait<1>();
        __syncthreads();
        if (tp + 2 < NTP) {
            const int stn = (st + 2 >= 3) ? st - 1 : st + 2;
            ISSUEW2(tp + 2, stn);
        }
        cp_commit();
        #pragma unroll
        for (int u = 0; u < 2; ++u) {
            const int t = 2 * tp + u;
            const uint32_t* Wc = Ws + st * 2 * BL_WSTAGE + u * BL_WSTAGE;
            const int i = t & 63;
            float D[2][2][4] = {};
            #pragma unroll
            for (int j0 = 0; j0 < 4; ++j0) {
                uint32_t bfp[2][2];
                #pragma unroll
                for (int nf = 0; nf < 2; ++nf) {
                    const int c = wn0 + nf * 8 + gid;
                    bfp[nf][0] = Wc[(j0 * 8 + tig) * BL_WSTRIDE + c];
                    bfp[nf][1] = Wc[(j0 * 8 + tig + 4) * BL_WSTRIDE + c];
                }
                #pragma unroll
                for (int mf = 0; mf < 2; ++mf)
                    #pragma unroll
                    for (int nf = 0; nf < 2; ++nf)
                        mma_f16(D[mf][nf], btf[mf][j0], bfp[nf]);
            }
            #pragma unroll
            for (int mf = 0; mf < 2; ++mf) {
                const float b0 = bh[(wm0 + mf * 16 + gid) * 68 + i];
                const float b1 = bh[(wm0 + mf * 16 + 8 + gid) * 68 + i];
                #pragma unroll
                for (int nf = 0; nf < 2; ++nf) {
                    acc[mf][nf][0] = fmaf(b0, D[mf][nf][0], acc[mf][nf][0]);
                    acc[mf][nf][1] = fmaf(b0, D[mf][nf][1], acc[mf][nf][1]);
                    acc[mf][nf][2] = fmaf(b1, D[mf][nf][2], acc[mf][nf][2]);
                    acc[mf][nf][3] = fmaf(b1, D[mf][nf][3], acc[mf][nf][3]);
                }
            }
            if (i == 63 && t + 1 < NBn * 64) {
                __syncthreads();
                LOADHT((t + 1) >> 6);
                __syncthreads();
                CACHEBT();
            }
        }
    }
#undef LOADHT
#undef ISSUEW2
#undef CACHEBT
    #pragma unroll
    for (int mf = 0; mf < 2; ++mf) {
        #pragma unroll
        for (int nf = 0; nf < 2; ++nf) {
            const int r = m0 + wm0 + mf * 16 + gid;
            const int c = n0 + wn0 + nf * 8 + tig * 2;
            if (r < M) {
                C[(long)r * 768 + c]     = acc[mf][nf][0] + bias[c];
                C[(long)r * 768 + c + 1] = acc[mf][nf][1] + bias[c + 1];
            }
            if (r + 8 < M) {
                C[(long)(r + 8) * 768 + c]     = acc[mf][nf][2] + bias[c];
                C[(long)(r + 8) * 768 + c + 1] = acc[mf][nf][3] + bias[c + 1];
            }
        }
    }
}

// ---------------- small fused kernels ----------------
__global__ void ent_emb_k(const float* __restrict__ seq, const int* __restrict__ midx,
                          const float* __restrict__ mmask, float* __restrict__ ent_emb)
{
    const int blk = blockIdx.x;
    const int b = blk / (MMn * NEn);
    const int idx = midx[blk];
    const float mask = mmask[blk];
    const float* src = seq + ((long)b * Cn + idx) * Hn;
    float* dst = ent_emb + (long)blk * Hn;
    for (int h = threadIdx.x; h < Hn; h += 256) dst[h] = mask * src[h];
}

__global__ void ent_att_k(const float* __restrict__ att, const int* __restrict__ midx,
                          const float* __restrict__ mmask, float* __restrict__ ent_att)
{
    const int blk = blockIdx.x;
    const int nh = blk % NHn;
    const int e  = (blk / NHn) % NEn;
    const int b  = blk / (NHn * NEn);
    const int c  = threadIdx.x;
    const int* mi = midx + (b * NEn + e) * MMn;
    const float* mk = mmask + (b * NEn + e) * MMn;
    float cnt = 0.f, s = 0.f;
    for (int m = 0; m < MMn; ++m) {
        const float w = mk[m];
        cnt += w;
        s += w * att[(((long)b * NHn + nh) * Cn + mi[m]) * Cn + c];
    }
    ent_att[(long)blk * Cn + c] = s / cnt;
}

__global__ void ht_att_k(const float* __restrict__ ent_att, const int* __restrict__ hts,
                         float* __restrict__ ht_att)
{
    const int bp = blockIdx.x;
    const int b = bp / Pn;
    const int hi = hts[bp * 2], ti = hts[bp * 2 + 1];
    const int c = threadIdx.x;
    const float* ha = ent_att + (long)(b * NEn + hi) * NHn * Cn;
    const float* ta = ent_att + (long)(b * NEn + ti) * NHn * Cn;
    float v = 0.f;
    #pragma unroll
    for (int nh = 0; nh < NHn; ++nh) v += ha[nh * Cn + c] * ta[nh * Cn + c];
    v *= (1.f / 12.f);
    __shared__ float red[512];
    red[c] = v; __syncthreads();
    for (int s = 256; s > 0; s >>= 1) { if (c < s) red[c] += red[c + s]; __syncthreads(); }
    ht_att[(long)bp * Cn + c] = v / (red[0] + 1e-5f);
}

__global__ void pool_attn_k(const float* __restrict__ htq, const float* __restrict__ ent_q,
                            const float* __restrict__ ent_emb, const float* __restrict__ mmask,
                            const int* __restrict__ hts, float* __restrict__ hs_att,
                            float* __restrict__ ts_att)
{
    const int bp = blockIdx.x;
    const int side = blockIdx.y;
    const int b = bp / Pn;
    const int e = hts[bp * 2 + side];
    __shared__ float qs[QSn];
    __shared__ float gs[MMn];
    const int tid = threadIdx.x;
    if (tid < QSn) qs[tid] = htq[(long)bp * QSn + tid];
    __syncthreads();
    if (tid < MMn) {
        const float* eq = ent_q + ((long)(b * NEn + e) * MMn + tid) * QSn;
        float d = 0.f;
        for (int i = 0; i < QSn; ++i) d += qs[i] * eq[i];
        const float mk = mmask[(b * NEn + e) * MMn + tid];
        gs[tid] = (mk > 0.f) ? d * SCALE_EMB : kNEG;
    }
    __syncthreads();
    float mx = -1e30f;
    for (int m = 0; m < MMn; ++m) mx = fmaxf(mx, gs[m]);
    float w[MMn]; float ssum = 0.f;
    for (int m = 0; m < MMn; ++m) { w[m] = expf(gs[m] - mx); ssum += w[m]; }
    const float inv = 1.f / ssum;
    const float* emb = ent_emb + (long)(b * NEn + e) * MMn * Hn;
    float* out = (side ? ts_att : hs_att) + (long)bp * Hn;
    for (int h = tid; h < Hn; h += 256) {
        float acc2 = 0.f;
        for (int m = 0; m < MMn; ++m) acc2 += w[m] * emb[m * Hn + h];
        out[h] = acc2 * inv;
    }
}

__global__ void cat2_k(const float* __restrict__ hs_att, const float* __restrict__ ts_att,
                       const float* __restrict__ rs, float* __restrict__ cat_h,
                       float* __restrict__ cat_t)
{
    const long r = blockIdx.x;
    for (int h = threadIdx.x; h < Hn; h += 256) {
        const float rv = rs[r * Hn + h];
        cat_h[r * 1536 + h]       = hs_att[r * Hn + h];
        cat_h[r * 1536 + 768 + h] = rv;
        cat_t[r * 1536 + h]       = ts_att[r * Hn + h];
        cat_t[r * 1536 + 768 + h] = rv;
    }
}

__global__ void catpp_k(const float* __restrict__ pairg, const float* __restrict__ pos_emb,
                        const int* __restrict__ hts, float* __restrict__ catpp)
{
    const long r = blockIdx.x;
    const int hi = hts[r * 2], ti = hts[r * 2 + 1];
    if (threadIdx.x < POSn) {
        catpp[r * 1024 + threadIdx.x]       = pos_emb[hi * POSn + threadIdx.x];
        catpp[r * 1024 + 896 + threadIdx.x] = pos_emb[ti * POSn + threadIdx.x];
    }
    for (int h = threadIdx.x; h < Hn; h += 256)
        catpp[r * 1024 + 128 + h] = pairg[r * Hn + h];
}

__global__ void pair_softmax_k(float* __restrict__ sc, const float* __restrict__ vis)
{
    const long bp = blockIdx.x;
    float* row = sc + bp * Pn;
    const float* vr = vis + bp * Pn;
    const int tid = threadIdx.x;
    __shared__ float red[128];
    float mx = -1e30f;
    for (int q = tid; q < Pn; q += 128) {
        const float v = (vr[q] > 0.f) ? row[q] : kNEG;
        mx = fmaxf(mx, v);
    }
    red[tid] = mx; __syncthreads();
    for (int s = 64; s > 0; s >>= 1) { if (tid < s) red[tid] = fmaxf(red[tid], red[tid + s]); __syncthreads(); }
    mx = red[0]; __syncthreads();
    float sum = 0.f;
    for (int q = tid; q < Pn; q += 128) {
        const float v = (vr[q] > 0.f) ? row[q] : kNEG;
        sum += expf(v - mx);
    }
    red[tid] = sum; __syncthreads();
    for (int s = 64; s > 0; s >>= 1) { if (tid < s) red[tid] += red[tid + s]; __syncthreads(); }
    const float inv = 1.f / red[0];
    for (int q = tid; q < Pn; q += 128) {
        const float v = (vr[q] > 0.f) ? row[q] : kNEG;
        row[q] = expf(v - mx) * inv;
    }
}

__global__ void catfeat_k(const float* __restrict__ hs, const float* __restrict__ ts,
                          const float* __restrict__ pair1, const float* __restrict__ atto,
                          float* __restrict__ catf)
{
    const long r = blockIdx.x;
    for (int h = threadIdx.x; h < Hn; h += 256) {
        catf[r * 2304 + h]        = hs[r * Hn + h];
        catf[r * 2304 + 768 + h]  = ts[r * Hn + h];
        catf[r * 2304 + 1536 + h] = pair1[r * Hn + h] + atto[r * Hn + h];
    }
}

// ---------------- launcher ----------------
extern "C" void kernel_launch(void* const* d_in, const int* in_sizes, int n_in,
                              void* d_out, int out_size)
{
    (void)in_sizes; (void)n_in; (void)out_size;
    const float* seq   = (const float*)d_in[0];
    const float* att   = (const float*)d_in[1];
    const int*   midx  = (const int*)  d_in[2];
    const float* mmask = (const float*)d_in[3];
    const int*   hts   = (const int*)  d_in[4];
    const float* vis   = (const float*)d_in[5];
    const float* Wcq = (const float*)d_in[6],  *bcq = (const float*)d_in[7];
    const float* Weq = (const float*)d_in[8],  *beq = (const float*)d_in[9];
    const float* Whe = (const float*)d_in[10], *bhe = (const float*)d_in[11];
    const float* Wte = (const float*)d_in[12], *bte = (const float*)d_in[13];
    const float* Wbl = (const float*)d_in[14], *bbl = (const float*)d_in[15];
    const float* Wpp = (const float*)d_in[16], *bpp = (const float*)d_in[17];
    const float* Wgq = (const float*)d_in[18];
    const float* Wgk = (const float*)d_in[19];
    const float* Wgv = (const float*)d_in[20];
    const float* Wp1 = (const float*)d_in[21], *bp1 = (const float*)d_in[22];
    const float* Wp2 = (const float*)d_in[23], *bp2 = (const float*)d_in[24];
    const float* pos = (const float*)d_in[25];
    float* out = (float*)d_out;

    float* base = nullptr;
    cudaGetSymbolAddress((void**)&base, g_scratch);
    float* ent_emb = base + OFF_ENT_EMB;
    float* ent_att = base + OFF_ENT_ATT;
    float* ent_q   = base + OFF_ENT_Q;
    float* ht_att  = base + OFF_HT_ATT;
    float* rs      = base + OFF_RS;
    float* htqb    = base + OFF_HTQ;
    float* hs_att  = base + OFF_HS_ATT;
    float* ts_att  = base + OFF_TS_ATT;
    float* cat_h   = base + OFF_CAT_H;
    float* hs_t    = base + OFF_HS;
    float* ts_t    = base + OFF_TS;
    float* pairg   = base + OFF_PAIRG;
    float* catpp   = base + OFF_CATPP;
    float* pair1   = base + OFF_PAIR1;
    float* qb      = base + OFF_QB;
    float* kb      = base + OFF_KB;
    float* vb      = base + OFF_VB;
    float* scb     = base + OFF_SC;
    float* atto    = base + OFF_ATTO;
    float* catf    = base + OFF_CATF;
    float* h1      = base + OFF_H1;
    float* wb      = base + OFF_WB;
    uint32_t* whf  = (uint32_t*)(base + OFF_WHF);
    uint32_t* wcqp = (uint32_t*)(base + OFF_WCQP);
    uint32_t* weqp = (uint32_t*)(base + OFF_WEQP);
    uint32_t* wcatp= (uint32_t*)(base + OFF_WCATP);
    uint32_t* wppp = (uint32_t*)(base + OFF_WPPP);
    uint32_t* wqkvp= (uint32_t*)(base + OFF_WQKVP);
    uint32_t* wp1p = (uint32_t*)(base + OFF_WP1P);

    cudaFuncSetAttribute(gemm_tc<false,false,false>, cudaFuncAttributeMaxDynamicSharedMemorySize, GT_SMEM);
    cudaFuncSetAttribute(gemm_tc<false,true,false>,  cudaFuncAttributeMaxDynamicSharedMemorySize, GT_SMEM);
    cudaFuncSetAttribute(gemm_tc<true,false,false>,  cudaFuncAttributeMaxDynamicSharedMemorySize, GT_SMEM);
    cudaFuncSetAttribute(gemm_f16w<true,false>,      cudaFuncAttributeMaxDynamicSharedMemorySize, GF_SMEM);
    cudaFuncSetAttribute(gemm_f16w<true,true>,       cudaFuncAttributeMaxDynamicSharedMemorySize, GF_SMEM);
    cudaFuncSetAttribute(gemm_f16w<false,false>,     cudaFuncAttributeMaxDynamicSharedMemorySize, GF_SMEM);
    cudaFuncSetAttribute(bilinear_tc, cudaFuncAttributeMaxDynamicSharedMemorySize, BL_SMEM);

    // 0) biases for batched z=2 launch; pre-pack ALL fp16 weights
    cudaMemcpyAsync(wb,       bhe, 768UL*4, cudaMemcpyDeviceToDevice);
    cudaMemcpyAsync(wb + 768, bte, 768UL*4, cudaMemcpyDeviceToDevice);
    conv_w_k<<<768, 256>>>(Wbl, whf);
    pack_w_k<<<384, 256>>>(Wcq, wcqp, 128);
    pack_w_k<<<384, 256>>>(Weq, weqp, 128);
    pack_w_k<<<768, 256>>>(Whe, wcatp, 768);
    pack_w_k<<<768, 256>>>(Wte, wcatp + 768UL*768, 768);
    pack_w_k<<<512, 256>>>(Wpp, wppp, 768);
    pack_w_k<<<384, 256>>>(Wgq, wqkvp, 768);
    pack_w_k<<<384, 256>>>(Wgk, wqkvp + 384UL*768, 768);
    pack_w_k<<<384, 256>>>(Wgv, wqkvp + 2UL*384*768, 768);
    pack_w_k<<<1152, 256>>>(Wp1, wp1p, 768);

    // 1) entity gathers
    ent_emb_k<<<Bn * NEn * MMn, 256>>>(seq, midx, mmask, ent_emb);
    ent_att_k<<<Bn * NEn * NHn, 512>>>(att, midx, mmask, ent_att);
    // 2) pair context attention
    ht_att_k<<<BPn, 512>>>(ent_att, hts, ht_att);
    // 3) rs = ht_att @ seq (batched, dynamic B -> tf32)
    gemm_tc<false,false,false><<<dim3(12, 6, 4), 256, GT_SMEM>>>(ht_att, seq, nullptr, rs,
        Pn, Hn, Cn, Cn, Hn, Hn, 380L*512, 512L*768, 380L*768, 1.f, 0L);
    // 4) htq, ent_q (fp16 packed weights)
    gemm_f16w<true,false><<<dim3(2, 24, 1), 256, GF_SMEM>>>(rs, wcqp, bcq, htqb,
        BPn, QSn, Hn, Hn, QSn, 0, 0, 0, 0L);
    gemm_f16w<true,false><<<dim3(2, 29, 1), 256, GF_SMEM>>>(ent_emb, weqp, beq, ent_q,
        1840, QSn, Hn, Hn, QSn, 0, 0, 0, 0L);
    // 5) mention-pool softmax
    pool_attn_k<<<dim3(BPn, 2), 256>>>(htqb, ent_q, ent_emb, mmask, hts, hs_att, ts_att);
    // 6) hs/ts projections — z=2 batched fp16 (per-z bias)
    cat2_k<<<BPn, 256>>>(hs_att, ts_att, rs, cat_h, base + OFF_CAT_T);
    gemm_f16w<true,true><<<dim3(12, 24, 2), 256, GF_SMEM>>>(cat_h, wcatp, wb, hs_t,
        BPn, EMBn, 1536, 1536, EMBn, 1520L*1536, 768L*768, 1520L*768, 768L);
    // 7) grouped bilinear
    bilinear_tc<<<dim3(12, 12), 512, BL_SMEM>>>(hs_t, ts_t, whf, bbl, pairg, BPn);
    // 8) pos concat + Wpp (fp16)
    catpp_k<<<BPn, 256>>>(pairg, pos, hts, catpp);
    gemm_f16w<true,true><<<dim3(12, 24, 1), 256, GF_SMEM>>>(catpp, wppp, bpp, pair1,
        BPn, EMBn, 1024, 1024, EMBn, 0, 0, 0, 0L);
    // 9) pair-graph attention: q/k/v fp16 z=3 batched
    gemm_f16w<false,false><<<dim3(12, 24, 3), 256, GF_SMEM>>>(pair1, wqkvp, nullptr, qb,
        BPn, EMBn, EMBn, EMBn, EMBn, 0, 384L*768, 1520L*768, 0L);
    gemm_tc<true,false,false><<<dim3(6, 6, 4), 256, GT_SMEM>>>(qb, kb, nullptr, scb,
        Pn, Pn, EMBn, EMBn, EMBn, Pn, 380L*768, 380L*768, 380L*380, SCALE_EMB, 0L);
    pair_softmax_k<<<BPn, 128>>>(scb, vis);
    gemm_tc<false,false,false><<<dim3(12, 6, 4), 256, GT_SMEM>>>(scb, vb, nullptr, atto,
        Pn, EMBn, Pn, Pn, EMBn, EMBn, 380L*380, 380L*768, 380L*768, 1.f, 0L);
    // 10) classifier head: Wp1 fp16, Wp2 tf32 (N=97)
    catfeat_k<<<BPn, 256>>>(hs_t, ts_t, pair1, atto, catf);
    gemm_f16w<true,true><<<dim3(12, 24, 1), 256, GF_SMEM>>>(catf, wp1p, bp1, h1,
        BPn, EMBn, 2304, 2304, EMBn, 0, 0, 0, 0L);
    gemm_tc<false,true,false><<<dim3(2, 24, 1), 256, GT_SMEM>>>(h1, Wp2, bp2, out,
        BPn, NCLSn, EMBn, EMBn, NCLSn, NCLSn, 0, 0, 0, 1.f, 0L);
}

// round 17
// speedup vs baseline: 1.1900x; 1.0083x over previous
#include <cuda_runtime.h>
#include <cuda_fp16.h>
#include <stdint.h>
#include <math.h>

// ---------------- problem constants ----------------
#define Bn   4
#define Cn   512
#define Hn   768
#define NHn  12
#define NEn  20
#define MMn  23
#define Pn   380
#define BPn  1520
#define QSn  128
#define EMBn 768
#define NBn  12
#define BLKn 64
#define NCLSn 97
#define POSn 128

static __device__ __constant__ float kNEG = -10000.0f;
#define SCALE_EMB 0.03608439182435161f   // 1/sqrt(768)

// ---------------- scratch ----------------
#define OFF_ENT_EMB 0UL
#define OFF_ENT_ATT (OFF_ENT_EMB + 1840UL*768)
#define OFF_ENT_Q   (OFF_ENT_ATT + 960UL*512)
#define OFF_HT_ATT  (OFF_ENT_Q   + 1840UL*128)
#define OFF_RS      (OFF_HT_ATT  + 1520UL*512)
#define OFF_HTQ     (OFF_RS      + 1520UL*768)
#define OFF_HS_ATT  (OFF_HTQ     + 1520UL*128)
#define OFF_TS_ATT  (OFF_HS_ATT  + 1520UL*768)
#define OFF_CAT_H   (OFF_TS_ATT  + 1520UL*768)
#define OFF_CAT_T   (OFF_CAT_H   + 1520UL*1536)
#define OFF_HS      (OFF_CAT_T   + 1520UL*1536)
#define OFF_TS      (OFF_HS      + 1520UL*768)
#define OFF_PAIRG   (OFF_TS      + 1520UL*768)
#define OFF_CATPP   (OFF_PAIRG   + 1520UL*768)
#define OFF_PAIR1   (OFF_CATPP   + 1520UL*1024)
#define OFF_QB      (OFF_PAIR1   + 1520UL*768)
#define OFF_KB      (OFF_QB      + 1520UL*768)
#define OFF_VB      (OFF_KB      + 1520UL*768)
#define OFF_SC      (OFF_VB      + 1520UL*768)
#define OFF_ATTO    (OFF_SC      + 4UL*380*380)
#define OFF_CATF    (OFF_ATTO    + 1520UL*768)
#define OFF_H1      (OFF_CATF    + 1520UL*2304)
#define OFF_WB      (OFF_H1      + 1520UL*768)
#define OFF_WHF     (OFF_WB      + 2UL*768)
#define OFF_WCQP    (OFF_WHF     + 768UL*24576)
#define OFF_WEQP    (OFF_WCQP    + 384UL*128)
#define OFF_WCATP   (OFF_WEQP    + 384UL*128)
#define OFF_WPPP    (OFF_WCATP   + 2UL*768*768)
#define OFF_WQKVP   (OFF_WPPP    + 512UL*768)
#define OFF_WP1P    (OFF_WQKVP   + 3UL*384*768)
#define OFF_QKP     (OFF_WP1P    + 1152UL*768)          // 3040*384 u32 (qb|kb packed)
#define OFF_VBP     (OFF_QKP     + 3040UL*384)          // 4*192*768 u32 (vb packed, padded)
#define OFF_SEQP    (OFF_VBP     + 4UL*192*768)         // 4*256*768 u32 (seq packed)
#define SCRATCH_TOTAL (OFF_SEQP  + 4UL*256*768)

__device__ float g_scratch[SCRATCH_TOTAL];

// ---------------- helpers ----------------
__device__ __forceinline__ uint32_t f2tf32(float x) {
    uint32_t r; asm("cvt.rna.tf32.f32 %0, %1;" : "=r"(r) : "f"(x)); return r;
}
__device__ __forceinline__ void mma_tf32(float* c, const uint32_t* a, const uint32_t* b) {
    asm volatile("mma.sync.aligned.m16n8k8.row.col.f32.tf32.tf32.f32 "
        "{%0,%1,%2,%3}, {%4,%5,%6,%7}, {%8,%9}, {%0,%1,%2,%3};"
        : "+f"(c[0]), "+f"(c[1]), "+f"(c[2]), "+f"(c[3])
        : "r"(a[0]), "r"(a[1]), "r"(a[2]), "r"(a[3]), "r"(b[0]), "r"(b[1]));
}
__device__ __forceinline__ uint32_t f2h2(float lo, float hi) {
    __half2 h = __floats2half2_rn(lo, hi);
    return *(uint32_t*)&h;
}
__device__ __forceinline__ void mma_f16(float* c, const uint32_t* a, const uint32_t* b) {
    asm volatile("mma.sync.aligned.m16n8k16.row.col.f32.f16.f16.f32 "
        "{%0,%1,%2,%3}, {%4,%5,%6,%7}, {%8,%9}, {%0,%1,%2,%3};"
        : "+f"(c[0]), "+f"(c[1]), "+f"(c[2]), "+f"(c[3])
        : "r"(a[0]), "r"(a[1]), "r"(a[2]), "r"(a[3]), "r"(b[0]), "r"(b[1]));
}
__device__ __forceinline__ void cp16(void* s, const void* g, int sz) {
    uint32_t sa = (uint32_t)__cvta_generic_to_shared(s);
    asm volatile("cp.async.cg.shared.global [%0], [%1], 16, %2;" :: "r"(sa), "l"(g), "r"(sz));
}
__device__ __forceinline__ void cp4(void* s, const void* g, int sz) {
    uint32_t sa = (uint32_t)__cvta_generic_to_shared(s);
    asm volatile("cp.async.ca.shared.global [%0], [%1], 4, %2;" :: "r"(sa), "l"(g), "r"(sz));
}
__device__ __forceinline__ void cp_commit() { asm volatile("cp.async.commit_group;"); }
template<int Ng> __device__ __forceinline__ void cp_wait() {
    asm volatile("cp.async.wait_group %0;" :: "n"(Ng));
}

#define GT_BM 64
#define GT_BN 64
#define GT_BK 32

// ---------------- tf32 GEMM (only Wp2 now): 64x64xBK32, 256 thr ----------------
#define GT_SMEM (3 * 2304 * 2 * 4)
template<bool TRANSB, bool BIAS, bool TANH>
__global__ __launch_bounds__(256, 2)
void gemm_tc(const float* __restrict__ A, const float* __restrict__ Bm,
             const float* __restrict__ bias, float* __restrict__ C,
             int M, int N, int K, int lda, int ldb, int ldc,
             long sA, long sB, long sC, float alpha, long sBias)
{
    extern __shared__ float sm[];
    float* As = sm;
    float* Bs = sm + 3 * 2304;
    const int tid = threadIdx.x;
    const int wid = tid >> 5, lane = tid & 31;
    const int gid = lane >> 2, tig = lane & 3;
    const int m0 = blockIdx.y * GT_BM, n0 = blockIdx.x * GT_BN;
    A  += (long)blockIdx.z * sA;
    Bm += (long)blockIdx.z * sB;
    C  += (long)blockIdx.z * sC;
    if (BIAS) bias += (long)blockIdx.z * sBias;
    const int wm0 = (wid & 3) * 16, wn0 = (wid >> 2) * 32;
    float acc[4][4] = {};
    const int ar = tid >> 2, akc = (tid & 3) * 8;
    const int bkr = tid >> 3, bnc = (tid & 7) * 8;
    const bool a_ok = (m0 + ar) < M;
    const bool b4 = (!TRANSB) && (((ldb & 3) != 0) || ((N & 3) != 0));
    const int nk = (K + GT_BK - 1) / GT_BK;

    auto issueA = [&](int kt, int st) {
        float* dst = As + st * 2304 + ar * 36 + akc;
        const float* src = A + (long)(m0 + ar) * lda + kt * GT_BK + akc;
        #pragma unroll
        for (int q = 0; q < 2; ++q) {
            int sz = (a_ok && (kt * GT_BK + akc + 4 * q) < K) ? 16 : 0;
            cp16(dst + 4 * q, src + 4 * q, sz);
        }
    };
    auto issueB = [&](int kt, int st) {
        if (!TRANSB) {
            float* dst = Bs + st * 2304 + bkr * 72 + bnc;
            const float* src = Bm + (long)(kt * GT_BK + bkr) * ldb + n0 + bnc;
            const bool kok = (kt * GT_BK + bkr) < K;
            if (!b4) {
                #pragma unroll
                for (int q = 0; q < 2; ++q) {
                    int sz = (kok && (n0 + bnc + 4 * q) < N) ? 16 : 0;
                    cp16(dst + 4 * q, src + 4 * q, sz);
                }
            } else {
                #pragma unroll
                for (int e = 0; e < 8; ++e) {
                    int sz = (kok && (n0 + bnc + e) < N) ? 4 : 0;
                    cp4(dst + e, src + e, sz);
                }
            }
        } else {
            float* dst = Bs + st * 2304 + ar * 36 + akc;
            const float* src = Bm + (long)(n0 + ar) * ldb + kt * GT_BK + akc;
            const bool nok = (n0 + ar) < N;
            #pragma unroll
            for (int q = 0; q < 2; ++q) {
                int sz = (nok && (kt * GT_BK + akc + 4 * q) < K) ? 16 : 0;
                cp16(dst + 4 * q, src + 4 * q, sz);
            }
        }
    };

    issueA(0, 0); issueB(0, 0); cp_commit();
    if (nk > 1) { issueA(1, 1); issueB(1, 1); }
    cp_commit();
    int st = 0;
    for (int kt = 0; kt < nk; ++kt) {
        cp_wait<1>();
        __syncthreads();
        const int ktn = kt + 2;
        if (ktn < nk) {
            const int stn = (st + 2 >= 3) ? st - 1 : st + 2;
            issueA(ktn, stn); issueB(ktn, stn);
        }
        cp_commit();
        const float* Ac = As + st * 2304;
        const float* Bc = Bs + st * 2304;
        #pragma unroll
        for (int kk = 0; kk < GT_BK; kk += 8) {
            uint32_t af[4], bf[4][2];
            af[0] = f2tf32(Ac[(wm0 + gid) * 36 + kk + tig]);
            af[1] = f2tf32(Ac[(wm0 + 8 + gid) * 36 + kk + tig]);
            af[2] = f2tf32(Ac[(wm0 + gid) * 36 + kk + tig + 4]);
            af[3] = f2tf32(Ac[(wm0 + 8 + gid) * 36 + kk + tig + 4]);
            #pragma unroll
            for (int nf = 0; nf < 4; ++nf) {
                const int c = wn0 + nf * 8 + gid;
                if (!TRANSB) {
                    bf[nf][0] = f2tf32(Bc[(kk + tig) * 72 + c]);
                    bf[nf][1] = f2tf32(Bc[(kk + tig + 4) * 72 + c]);
                } else {
                    bf[nf][0] = f2tf32(Bc[c * 36 + kk + tig]);
                    bf[nf][1] = f2tf32(Bc[c * 36 + kk + tig + 4]);
                }
            }
            #pragma unroll
            for (int nf = 0; nf < 4; ++nf)
                mma_tf32(acc[nf], af, bf[nf]);
        }
        st = (st + 1 >= 3) ? 0 : st + 1;
    }
    #pragma unroll
    for (int nf = 0; nf < 4; ++nf) {
        const int r = m0 + wm0 + gid;
        const int c = n0 + wn0 + nf * 8 + tig * 2;
        #pragma unroll
        for (int half = 0; half < 2; ++half) {
            const int rr = r + half * 8;
            if (rr >= M) continue;
            #pragma unroll
            for (int j = 0; j < 2; ++j) {
                const int cc = c + j;
                if (cc >= N) continue;
                float v = acc[nf][half * 2 + j] * alpha;
                if (BIAS) v += bias[cc];
                if (TANH) v = tanhf(v);
                C[(long)rr * ldc + cc] = v;
            }
        }
    }
}

// ---------------- fp16 GEMM, pre-packed half2 B: 64x64xBK32, 256 thr ----------------
// Bp: [ceil(K/32)*16][N] u32 (zero-padded beyond K). N%64==0.
#define GF_SMEM ((3 * 2304 + 3 * 1152) * 4)
template<bool BIAS, bool TANH>
__global__ __launch_bounds__(256, 2)
void gemm_f16w(const float* __restrict__ A, const uint32_t* __restrict__ Bp,
               const float* __restrict__ bias, float* __restrict__ C,
               int M, int N, int K, int lda, int ldc,
               long sA, long sB, long sC, long sBias)
{
    extern __shared__ float sm[];
    float* As = sm;
    uint32_t* Bsp = (uint32_t*)(sm + 3 * 2304);
    const int tid = threadIdx.x;
    const int wid = tid >> 5, lane = tid & 31;
    const int gid = lane >> 2, tig = lane & 3;
    const int m0 = blockIdx.y * GT_BM, n0 = blockIdx.x * GT_BN;
    A  += (long)blockIdx.z * sA;
    Bp += (long)blockIdx.z * sB;
    C  += (long)blockIdx.z * sC;
    if (BIAS) bias += (long)blockIdx.z * sBias;
    const int wm0 = (wid & 3) * 16, wn0 = (wid >> 2) * 32;
    float acc[4][4] = {};
    const int ar = tid >> 2, akc = (tid & 3) * 8;
    const int bkr = tid >> 4, bnc = (tid & 15) * 4;
    const bool a_ok = (m0 + ar) < M;
    const int nk = (K + GT_BK - 1) / GT_BK;

    auto issueA = [&](int kt, int st) {
        float* dst = As + st * 2304 + ar * 36 + akc;
        const float* src = A + (long)(m0 + ar) * lda + kt * GT_BK + akc;
        #pragma unroll
        for (int q = 0; q < 2; ++q) {
            int sz = (a_ok && (kt * GT_BK + akc + 4 * q) < K) ? 16 : 0;
            cp16(dst + 4 * q, src + 4 * q, sz);
        }
    };
    auto issueB = [&](int kt, int st) {
        uint32_t* dst = Bsp + st * 1152 + bkr * 72 + bnc;
        const uint32_t* src = Bp + (long)(kt * 16 + bkr) * N + n0 + bnc;
        cp16(dst, src, 16);
    };

    issueA(0, 0); issueB(0, 0); cp_commit();
    if (nk > 1) { issueA(1, 1); issueB(1, 1); }
    cp_commit();
    int st = 0;
    for (int kt = 0; kt < nk; ++kt) {
        cp_wait<1>();
        __syncthreads();
        const int ktn = kt + 2;
        if (ktn < nk) {
            const int stn = (st + 2 >= 3) ? st - 1 : st + 2;
            issueA(ktn, stn); issueB(ktn, stn);
        }
        cp_commit();
        const float* Ac = As + st * 2304;
        const uint32_t* Bc = Bsp + st * 1152;
        #pragma unroll
        for (int kk = 0; kk < GT_BK; kk += 16) {
            const int k0 = kk + tig * 2;
            const int pb = (kk >> 1) + tig;
            uint32_t af[4], bf[4][2];
            {
                const float* r0 = Ac + (wm0 + gid) * 36;
                const float* r1 = Ac + (wm0 + 8 + gid) * 36;
                af[0] = f2h2(r0[k0], r0[k0 + 1]);
                af[1] = f2h2(r1[k0], r1[k0 + 1]);
                af[2] = f2h2(r0[k0 + 8], r0[k0 + 9]);
                af[3] = f2h2(r1[k0 + 8], r1[k0 + 9]);
            }
            #pragma unroll
            for (int nf = 0; nf < 4; ++nf) {
                const int c = wn0 + nf * 8 + gid;
                bf[nf][0] = Bc[pb * 72 + c];
                bf[nf][1] = Bc[(pb + 4) * 72 + c];
            }
            #pragma unroll
            for (int nf = 0; nf < 4; ++nf)
                mma_f16(acc[nf], af, bf[nf]);
        }
        st = (st + 1 >= 3) ? 0 : st + 1;
    }
    #pragma unroll
    for (int nf = 0; nf < 4; ++nf) {
        const int r = m0 + wm0 + gid;
        const int c = n0 + wn0 + nf * 8 + tig * 2;
        #pragma unroll
        for (int half = 0; half < 2; ++half) {
            const int rr = r + half * 8;
            if (rr >= M) continue;
            #pragma unroll
            for (int j = 0; j < 2; ++j) {
                const int cc = c + j;
                if (cc >= N) continue;
                float v = acc[nf][half * 2 + j];
                if (BIAS) v += bias[cc];
                if (TANH) v = tanhf(v);
                C[(long)rr * ldc + cc] = v;
            }
        }
    }
}

// ---------------- fp16 sc GEMM: both operands packed along K ----------------
// C[m,n] = alpha * sum_k A[m,k]*B[n,k]; Ap/Bp: [rows][KP] u32 (KP=K/2), per-z offsets.
#define GS_SMEM (2 * 3 * 1280 * 4)
__global__ __launch_bounds__(256, 2)
void gemm_f16sc(const uint32_t* __restrict__ Ap, const uint32_t* __restrict__ Bp,
                float* __restrict__ C, int M, int N, int K, int KP,
                long sA, long sB, long sC, float alpha)
{
    extern __shared__ float sm[];
    uint32_t* Asp = (uint32_t*)sm;               // [3][64][20]
    uint32_t* Bsp = (uint32_t*)sm + 3 * 1280;    // [3][64][20]
    const int tid = threadIdx.x;
    const int wid = tid >> 5, lane = tid & 31;
    const int gid = lane >> 2, tig = lane & 3;
    const int m0 = blockIdx.y * GT_BM, n0 = blockIdx.x * GT_BN;
    Ap += (long)blockIdx.z * sA;
    Bp += (long)blockIdx.z * sB;
    C  += (long)blockIdx.z * sC;
    const int wm0 = (wid & 3) * 16, wn0 = (wid >> 2) * 32;
    float acc[4][4] = {};
    const int ar = tid >> 2, ac = (tid & 3) * 4;     // 64 rows x 16 u32
    const bool a_ok = (m0 + ar) < M;
    const bool b_ok = (n0 + ar) < N;
    const int nk = K / GT_BK;                        // K%32==0

    auto issueA = [&](int kt, int st) {
        uint32_t* dst = Asp + st * 1280 + ar * 20 + ac;
        const uint32_t* src = Ap + (long)(m0 + ar) * KP + kt * 16 + ac;
        cp16(dst, src, a_ok ? 16 : 0);
    };
    auto issueB = [&](int kt, int st) {
        uint32_t* dst = Bsp + st * 1280 + ar * 20 + ac;
        const uint32_t* src = Bp + (long)(n0 + ar) * KP + kt * 16 + ac;
        cp16(dst, src, b_ok ? 16 : 0);
    };

    issueA(0, 0); issueB(0, 0); cp_commit();
    if (nk > 1) { issueA(1, 1); issueB(1, 1); }
    cp_commit();
    int st = 0;
    for (int kt = 0; kt < nk; ++kt) {
        cp_wait<1>();
        __syncthreads();
        const int ktn = kt + 2;
        if (ktn < nk) {
            const int stn = (st + 2 >= 3) ? st - 1 : st + 2;
            issueA(ktn, stn); issueB(ktn, stn);
        }
        cp_commit();
        const uint32_t* Acp = Asp + st * 1280;
        const uint32_t* Bcp = Bsp + st * 1280;
        #pragma unroll
        for (int kk = 0; kk < GT_BK; kk += 16) {
            const int pb = (kk >> 1) + tig;
            uint32_t af[4], bf[4][2];
            af[0] = Acp[(wm0 + gid) * 20 + pb];
            af[1] = Acp[(wm0 + 8 + gid) * 20 + pb];
            af[2] = Acp[(wm0 + gid) * 20 + pb + 4];
            af[3] = Acp[(wm0 + 8 + gid) * 20 + pb + 4];
            #pragma unroll
            for (int nf = 0; nf < 4; ++nf) {
                const int c = wn0 + nf * 8 + gid;
                bf[nf][0] = Bcp[c * 20 + pb];
                bf[nf][1] = Bcp[c * 20 + pb + 4];
            }
            #pragma unroll
            for (int nf = 0; nf < 4; ++nf)
                mma_f16(acc[nf], af, bf[nf]);
        }
        st = (st + 1 >= 3) ? 0 : st + 1;
    }
    #pragma unroll
    for (int nf = 0; nf < 4; ++nf) {
        const int r = m0 + wm0 + gid;
        const int c = n0 + wn0 + nf * 8 + tig * 2;
        #pragma unroll
        for (int half = 0; half < 2; ++half) {
            const int rr = r + half * 8;
            if (rr >= M) continue;
            #pragma unroll
            for (int j = 0; j < 2; ++j) {
                const int cc = c + j;
                if (cc >= N) continue;
                C[(long)rr * N + cc] = acc[nf][half * 2 + j] * alpha;
            }
        }
    }
}

// ---------------- pack kernels ----------------
// weight pack: [K][N] fp32 -> [K/2][N] u32
__global__ __launch_bounds__(256)
void pack_w_k(const float* __restrict__ W, uint32_t* __restrict__ out, int N)
{
    const int p = blockIdx.x;
    const float* r0 = W + (long)(2 * p) * N;
    const float* r1 = r0 + N;
    for (int c = threadIdx.x; c < N; c += 256)
        out[(long)p * N + c] = f2h2(r0[c], r1[c]);
}
// 3 weights at once (same shape), z selects
__global__ __launch_bounds__(256)
void pack_w3_k(const float* __restrict__ W0, const float* __restrict__ W1,
               const float* __restrict__ W2, uint32_t* __restrict__ out, int N, long ostride)
{
    const float* W = (blockIdx.y == 0) ? W0 : (blockIdx.y == 1) ? W1 : W2;
    const int p = blockIdx.x;
    const float* r0 = W + (long)(2 * p) * N;
    const float* r1 = r0 + N;
    uint32_t* o = out + blockIdx.y * ostride;
    for (int c = threadIdx.x; c < N; c += 256)
        o[(long)p * N + c] = f2h2(r0[c], r1[c]);
}
// pack rows along columns: [R][C] fp32 -> [R][C/2] u32 (for qb|kb)
__global__ __launch_bounds__(256)
void pack_rows_k(const float* __restrict__ in, uint32_t* __restrict__ out, int C)
{
    const long r = blockIdx.x;
    const float* src = in + r * C;
    uint32_t* dst = out + r * (C / 2);
    for (int p = threadIdx.x; p < C / 2; p += 256)
        dst[p] = f2h2(src[2 * p], src[2 * p + 1]);
}
// pack along K with zero pad: per z: [K][C] -> [KProws][C] u32
__global__ __launch_bounds__(256)
void pack_kdim_k(const float* __restrict__ in, uint32_t* __restrict__ out,
                 int K, int KProws, int C)
{
    const int p = blockIdx.x;
    const float* src = in + (long)blockIdx.y * K * C;
    uint32_t* dst = out + ((long)blockIdx.y * KProws + p) * C;
    const int r0 = 2 * p, r1 = 2 * p + 1;
    for (int c = threadIdx.x; c < C; c += 256) {
        float v0 = (r0 < K) ? src[(long)r0 * C + c] : 0.f;
        float v1 = (r1 < K) ? src[(long)r1 * C + c] : 0.f;
        dst[c] = f2h2(v0, v1);
    }
}
// bilinear W pre-convert: [49152][768] -> [768][32][768] u32
__global__ __launch_bounds__(256)
void conv_w_k(const float* __restrict__ W, uint32_t* __restrict__ Whf)
{
    const int t = blockIdx.x;
    const int tid = threadIdx.x;
    const float* Wt = W + (long)t * 64 * 768;
    uint32_t* Dt = Whf + (long)t * 24576;
    #pragma unroll 1
    for (int p = 0; p < 32; ++p) {
        const float* r0 = Wt + (2 * p) * 768;
        const float* r1 = Wt + (2 * p + 1) * 768;
        #pragma unroll
        for (int j = 0; j < 3; ++j) {
            const int c = tid + j * 256;
            Dt[p * 768 + c] = f2h2(r0[c], r1[c]);
        }
    }
}

// ---------------- bilinear: fp16 mma, pre-packed half2 W, 512 thr, 2-step stages ----------------
#define BL_WSTRIDE 72
#define BL_WSTAGE  (32 * BL_WSTRIDE)
#define BL_SMEM    ((2*128*68 + 3*2*BL_WSTAGE) * 4)
__global__ __launch_bounds__(512)
void bilinear_tc(const float* __restrict__ Hs, const float* __restrict__ Ts,
                 const uint32_t* __restrict__ Whf, const float* __restrict__ bias,
                 float* __restrict__ C, int M)
{
    extern __shared__ float sm[];
    float* bh = sm;
    float* bt = sm + 128 * 68;
    uint32_t* Ws = (uint32_t*)(sm + 2 * 128 * 68);
    const int tid = threadIdx.x;
    const int wid = tid >> 5, lane = tid & 31;
    const int gid = lane >> 2, tig = lane & 3;
    const int m0 = blockIdx.y * 128, n0 = blockIdx.x * 64;
    const int wm0 = (wid & 3) * 32, wn0 = (wid >> 2) * 16;
    float acc[2][2][4] = {};
    const int lr = tid >> 2, lc = (tid & 3) * 16;
    const bool lok = (m0 + lr) < M;
    uint32_t btf[2][4][4];
    const int NTP = NBn * 32;

#define LOADHT(nb_) { \
    const float* hp = Hs + (long)(m0 + lr) * 768 + (nb_) * 64 + lc; \
    const float* tp = Ts + (long)(m0 + lr) * 768 + (nb_) * 64 + lc; \
    _Pragma("unroll") for (int q_ = 0; q_ < 4; ++q_) { \
        float4 hv = lok ? *(const float4*)(hp + 4 * q_) : make_float4(0, 0, 0, 0); \
        float4 tv = lok ? *(const float4*)(tp + 4 * q_) : make_float4(0, 0, 0, 0); \
        *(float4*)&bh[lr * 68 + lc + 4 * q_] = hv; \
        *(float4*)&bt[lr * 68 + lc + 4 * q_] = tv; } }

#define ISSUEW2(tp_, st_) { \
    if (tid < 256) { \
        const int half_ = tid >> 7, id_ = tid & 127; \
        const int wr_ = id_ >> 2, wq_ = id_ & 3; \
        uint32_t* dst_ = Ws + (st_) * 2 * BL_WSTAGE + half_ * BL_WSTAGE + wr_ * BL_WSTRIDE + wq_ * 16; \
        const uint32_t* src_ = Whf + (long)(2 * (tp_) + half_) * 24576 + wr_ * 768 + n0 + wq_ * 16; \
        cp16(dst_, src_, 16); cp16(dst_ + 4, src_ + 4, 16); \
        cp16(dst_ + 8, src_ + 8, 16); cp16(dst_ + 12, src_ + 12, 16); } }

#define CACHEBT() { \
    _Pragma("unroll") for (int mf_ = 0; mf_ < 2; ++mf_) { const int r0_ = wm0 + mf_ * 16; \
        _Pragma("unroll") for (int j0_ = 0; j0_ < 4; ++j0_) { \
            const int k0_ = j0_ * 16 + tig * 2; \
            btf[mf_][j0_][0] = f2h2(bt[(r0_ + gid) * 68 + k0_],     bt[(r0_ + gid) * 68 + k0_ + 1]); \
            btf[mf_][j0_][1] = f2h2(bt[(r0_ + 8 + gid) * 68 + k0_], bt[(r0_ + 8 + gid) * 68 + k0_ + 1]); \
            btf[mf_][j0_][2] = f2h2(bt[(r0_ + gid) * 68 + k0_ + 8], bt[(r0_ + gid) * 68 + k0_ + 9]); \
            btf[mf_][j0_][3] = f2h2(bt[(r0_ + 8 + gid) * 68 + k0_ + 8], bt[(r0_ + 8 + gid) * 68 + k0_ + 9]); } } }

    LOADHT(0);
    ISSUEW2(0, 0); cp_commit();
    ISSUEW2(1, 1); cp_commit();
    __syncthreads();
    CACHEBT();

    for (int tp = 0; tp < NTP; ++tp) {
        const int st = tp % 3;
        cp_wait<1>();
        __syncthreads();
        if (tp + 2 < NTP) {
            const int stn = (st + 2 >= 3) ? st - 1 : st + 2;
            ISSUEW2(tp + 2, stn);
        }
        cp_commit();
        #pragma unroll
        for (int u = 0; u < 2; ++u) {
            const int t = 2 * tp + u;
            const uint32_t* Wc = Ws + st * 2 * BL_WSTAGE + u * BL_WSTAGE;
            const int i = t & 63;
            float D[2][2][4] = {};
            #pragma unroll
            for (int j0 = 0; j0 < 4; ++j0) {
                uint32_t bfp[2][2];
                #pragma unroll
                for (int nf = 0; nf < 2; ++nf) {
                    const int c = wn0 + nf * 8 + gid;
                    bfp[nf][0] = Wc[(j0 * 8 + tig) * BL_WSTRIDE + c];
                    bfp[nf][1] = Wc[(j0 * 8 + tig + 4) * BL_WSTRIDE + c];
                }
                #pragma unroll
                for (int mf = 0; mf < 2; ++mf)
                    #pragma unroll
                    for (int nf = 0; nf < 2; ++nf)
                        mma_f16(D[mf][nf], btf[mf][j0], bfp[nf]);
            }
            #pragma unroll
            for (int mf = 0; mf < 2; ++mf) {
                const float b0 = bh[(wm0 + mf * 16 + gid) * 68 + i];
                const float b1 = bh[(wm0 + mf * 16 + 8 + gid) * 68 + i];
                #pragma unroll
                for (int nf = 0; nf < 2; ++nf) {
                    acc[mf][nf][0] = fmaf(b0, D[mf][nf][0], acc[mf][nf][0]);
                    acc[mf][nf][1] = fmaf(b0, D[mf][nf][1], acc[mf][nf][1]);
                    acc[mf][nf][2] = fmaf(b1, D[mf][nf][2], acc[mf][nf][2]);
                    acc[mf][nf][3] = fmaf(b1, D[mf][nf][3], acc[mf][nf][3]);
                }
            }
            if (i == 63 && t + 1 < NBn * 64) {
                __syncthreads();
                LOADHT((t + 1) >> 6);
                __syncthreads();
                CACHEBT();
            }
        }
    }
#undef LOADHT
#undef ISSUEW2
#undef CACHEBT
    #pragma unroll
    for (int mf = 0; mf < 2; ++mf) {
        #pragma unroll
        for (int nf = 0; nf < 2; ++nf) {
            const int r = m0 + wm0 + mf * 16 + gid;
            const int c = n0 + wn0 + nf * 8 + tig * 2;
            if (r < M) {
                C[(long)r * 768 + c]     = acc[mf][nf][0] + bias[c];
                C[(long)r * 768 + c + 1] = acc[mf][nf][1] + bias[c + 1];
            }
            if (r + 8 < M) {
                C[(long)(r + 8) * 768 + c]     = acc[mf][nf][2] + bias[c];
                C[(long)(r + 8) * 768 + c + 1] = acc[mf][nf][3] + bias[c + 1];
            }
        }
    }
}

// ---------------- small fused kernels ----------------
__global__ void ent_emb_k(const float* __restrict__ seq, const int* __restrict__ midx,
                          const float* __restrict__ mmask, float* __restrict__ ent_emb)
{
    const int blk = blockIdx.x;
    const int b = blk / (MMn * NEn);
    const int idx = midx[blk];
    const float mask = mmask[blk];
    const float* src = seq + ((long)b * Cn + idx) * Hn;
    float* dst = ent_emb + (long)blk * Hn;
    for (int h = threadIdx.x; h < Hn; h += 256) dst[h] = mask * src[h];
}

__global__ void ent_att_k(const float* __restrict__ att, const int* __restrict__ midx,
                          const float* __restrict__ mmask, float* __restrict__ ent_att)
{
    const int blk = blockIdx.x;
    const int nh = blk % NHn;
    const int e  = (blk / NHn) % NEn;
    const int b  = blk / (NHn * NEn);
    const int c  = threadIdx.x;
    const int* mi = midx + (b * NEn + e) * MMn;
    const float* mk = mmask + (b * NEn + e) * MMn;
    float cnt = 0.f, s = 0.f;
    for (int m = 0; m < MMn; ++m) {
        const float w = mk[m];
        cnt += w;
        s += w * att[(((long)b * NHn + nh) * Cn + mi[m]) * Cn + c];
    }
    ent_att[(long)blk * Cn + c] = s / cnt;
}

__global__ void ht_att_k(const float* __restrict__ ent_att, const int* __restrict__ hts,
                         float* __restrict__ ht_att)
{
    const int bp = blockIdx.x;
    const int b = bp / Pn;
    const int hi = hts[bp * 2], ti = hts[bp * 2 + 1];
    const int c = threadIdx.x;
    const float* ha = ent_att + (long)(b * NEn + hi) * NHn * Cn;
    const float* ta = ent_att + (long)(b * NEn + ti) * NHn * Cn;
    float v = 0.f;
    #pragma unroll
    for (int nh = 0; nh < NHn; ++nh) v += ha[nh * Cn + c] * ta[nh * Cn + c];
    v *= (1.f / 12.f);
    __shared__ float red[512];
    red[c] = v; __syncthreads();
    for (int s = 256; s > 0; s >>= 1) { if (c < s) red[c] += red[c + s]; __syncthreads(); }
    ht_att[(long)bp * Cn + c] = v / (red[0] + 1e-5f);
}

__global__ void pool_attn_k(const float* __restrict__ htq, const float* __restrict__ ent_q,
                            const float* __restrict__ ent_emb, const float* __restrict__ mmask,
                            const int* __restrict__ hts, float* __restrict__ hs_att,
                            float* __restrict__ ts_att)
{
    const int bp = blockIdx.x;
    const int side = blockIdx.y;
    const int b = bp / Pn;
    const int e = hts[bp * 2 + side];
    __shared__ float qs[QSn];
    __shared__ float gs[MMn];
    const int tid = threadIdx.x;
    if (tid < QSn) qs[tid] = htq[(long)bp * QSn + tid];
    __syncthreads();
    if (tid < MMn) {
        const float* eq = ent_q + ((long)(b * NEn + e) * MMn + tid) * QSn;
        float d = 0.f;
        for (int i = 0; i < QSn; ++i) d += qs[i] * eq[i];
        const float mk = mmask[(b * NEn + e) * MMn + tid];
        gs[tid] = (mk > 0.f) ? d * SCALE_EMB : kNEG;
    }
    __syncthreads();
    float mx = -1e30f;
    for (int m = 0; m < MMn; ++m) mx = fmaxf(mx, gs[m]);
    float w[MMn]; float ssum = 0.f;
    for (int m = 0; m < MMn; ++m) { w[m] = expf(gs[m] - mx); ssum += w[m]; }
    const float inv = 1.f / ssum;
    const float* emb = ent_emb + (long)(b * NEn + e) * MMn * Hn;
    float* out = (side ? ts_att : hs_att) + (long)bp * Hn;
    for (int h = tid; h < Hn; h += 256) {
        float acc2 = 0.f;
        for (int m = 0; m < MMn; ++m) acc2 += w[m] * emb[m * Hn + h];
        out[h] = acc2 * inv;
    }
}

__global__ void cat2_k(const float* __restrict__ hs_att, const float* __restrict__ ts_att,
                       const float* __restrict__ rs, float* __restrict__ cat_h,
                       float* __restrict__ cat_t)
{
    const long r = blockIdx.x;
    for (int h = threadIdx.x; h < Hn; h += 256) {
        const float rv = rs[r * Hn + h];
        cat_h[r * 1536 + h]       = hs_att[r * Hn + h];
        cat_h[r * 1536 + 768 + h] = rv;
        cat_t[r * 1536 + h]       = ts_att[r * Hn + h];
        cat_t[r * 1536 + 768 + h] = rv;
    }
}

__global__ void catpp_k(const float* __restrict__ pairg, const float* __restrict__ pos_emb,
                        const int* __restrict__ hts, float* __restrict__ catpp)
{
    const long r = blockIdx.x;
    const int hi = hts[r * 2], ti = hts[r * 2 + 1];
    if (threadIdx.x < POSn) {
        catpp[r * 1024 + threadIdx.x]       = pos_emb[hi * POSn + threadIdx.x];
        catpp[r * 1024 + 896 + threadIdx.x] = pos_emb[ti * POSn + threadIdx.x];
    }
    for (int h = threadIdx.x; h < Hn; h += 256)
        catpp[r * 1024 + 128 + h] = pairg[r * Hn + h];
}

__global__ void pair_softmax_k(float* __restrict__ sc, const float* __restrict__ vis)
{
    const long bp = blockIdx.x;
    float* row = sc + bp * Pn;
    const float* vr = vis + bp * Pn;
    const int tid = threadIdx.x;
    __shared__ float red[128];
    float mx = -1e30f;
    for (int q = tid; q < Pn; q += 128) {
        const float v = (vr[q] > 0.f) ? row[q] : kNEG;
        mx = fmaxf(mx, v);
    }
    red[tid] = mx; __syncthreads();
    for (int s = 64; s > 0; s >>= 1) { if (tid < s) red[tid] = fmaxf(red[tid], red[tid + s]); __syncthreads(); }
    mx = red[0]; __syncthreads();
    float sum = 0.f;
    for (int q = tid; q < Pn; q += 128) {
        const float v = (vr[q] > 0.f) ? row[q] : kNEG;
        sum += expf(v - mx);
    }
    red[tid] = sum; __syncthreads();
    for (int s = 64; s > 0; s >>= 1) { if (tid < s) red[tid] += red[tid + s]; __syncthreads(); }
    const float inv = 1.f / red[0];
    for (int q = tid; q < Pn; q += 128) {
        const float v = (vr[q] > 0.f) ? row[q] : kNEG;
        row[q] = expf(v - mx) * inv;
    }
}

__global__ void catfeat_k(const float* __restrict__ hs, const float* __restrict__ ts,
                          const float* __restrict__ pair1, const float* __restrict__ atto,
                          float* __restrict__ catf)
{
    const long r = blockIdx.x;
    for (int h = threadIdx.x; h < Hn; h += 256) {
        catf[r * 2304 + h]        = hs[r * Hn + h];
        catf[r * 2304 + 768 + h]  = ts[r * Hn + h];
        catf[r * 2304 + 1536 + h] = pair1[r * Hn + h] + atto[r * Hn + h];
    }
}

// ---------------- launcher ----------------
extern "C" void kernel_launch(void* const* d_in, const int* in_sizes, int n_in,
                              void* d_out, int out_size)
{
    (void)in_sizes; (void)n_in; (void)out_size;
    const float* seq   = (const float*)d_in[0];
    const float* att   = (const float*)d_in[1];
    const int*   midx  = (const int*)  d_in[2];
    const float* mmask = (const float*)d_in[3];
    const int*   hts   = (const int*)  d_in[4];
    const float* vis   = (const float*)d_in[5];
    const float* Wcq = (const float*)d_in[6],  *bcq = (const float*)d_in[7];
    const float* Weq = (const float*)d_in[8],  *beq = (const float*)d_in[9];
    const float* Whe = (const float*)d_in[10], *bhe = (const float*)d_in[11];
    const float* Wte = (const float*)d_in[12], *bte = (const float*)d_in[13];
    const float* Wbl = (const float*)d_in[14], *bbl = (const float*)d_in[15];
    const float* Wpp = (const float*)d_in[16], *bpp = (const float*)d_in[17];
    const float* Wgq = (const float*)d_in[18];
    const float* Wgk = (const float*)d_in[19];
    const float* Wgv = (const float*)d_in[20];
    const float* Wp1 = (const float*)d_in[21], *bp1 = (const float*)d_in[22];
    const float* Wp2 = (const float*)d_in[23], *bp2 = (const float*)d_in[24];
    const float* pos = (const float*)d_in[25];
    float* out = (float*)d_out;

    float* base = nullptr;
    cudaGetSymbolAddress((void**)&base, g_scratch);
    float* ent_emb = base + OFF_ENT_EMB;
    float* ent_att = base + OFF_ENT_ATT;
    float* ent_q   = base + OFF_ENT_Q;
    float* ht_att  = base + OFF_HT_ATT;
    float* rs      = base + OFF_RS;
    float* htqb    = base + OFF_HTQ;
    float* hs_att  = base + OFF_HS_ATT;
    float* ts_att  = base + OFF_TS_ATT;
    float* cat_h   = base + OFF_CAT_H;
    float* hs_t    = base + OFF_HS;
    float* ts_t    = base + OFF_TS;
    float* pairg   = base + OFF_PAIRG;
    float* catpp   = base + OFF_CATPP;
    float* pair1   = base + OFF_PAIR1;
    float* qb      = base + OFF_QB;
    float* kb      = base + OFF_KB;
    float* vb      = base + OFF_VB;
    float* scb     = base + OFF_SC;
    float* atto    = base + OFF_ATTO;
    float* catf    = base + OFF_CATF;
    float* h1      = base + OFF_H1;
    float* wb      = base + OFF_WB;
    uint32_t* whf  = (uint32_t*)(base + OFF_WHF);
    uint32_t* wcqp = (uint32_t*)(base + OFF_WCQP);
    uint32_t* weqp = (uint32_t*)(base + OFF_WEQP);
    uint32_t* wcatp= (uint32_t*)(base + OFF_WCATP);
    uint32_t* wppp = (uint32_t*)(base + OFF_WPPP);
    uint32_t* wqkvp= (uint32_t*)(base + OFF_WQKVP);
    uint32_t* wp1p = (uint32_t*)(base + OFF_WP1P);
    uint32_t* qkp  = (uint32_t*)(base + OFF_QKP);
    uint32_t* vbp  = (uint32_t*)(base + OFF_VBP);
    uint32_t* seqp = (uint32_t*)(base + OFF_SEQP);

    cudaFuncSetAttribute(gemm_tc<false,true,false>,  cudaFuncAttributeMaxDynamicSharedMemorySize, GT_SMEM);
    cudaFuncSetAttribute(gemm_f16w<true,false>,      cudaFuncAttributeMaxDynamicSharedMemorySize, GF_SMEM);
    cudaFuncSetAttribute(gemm_f16w<true,true>,       cudaFuncAttributeMaxDynamicSharedMemorySize, GF_SMEM);
    cudaFuncSetAttribute(gemm_f16w<false,false>,     cudaFuncAttributeMaxDynamicSharedMemorySize, GF_SMEM);
    cudaFuncSetAttribute(gemm_f16sc,                 cudaFuncAttributeMaxDynamicSharedMemorySize, GS_SMEM);
    cudaFuncSetAttribute(bilinear_tc, cudaFuncAttributeMaxDynamicSharedMemorySize, BL_SMEM);

    // 0) biases; pre-pack all static weights + seq
    cudaMemcpyAsync(wb,       bhe, 768UL*4, cudaMemcpyDeviceToDevice);
    cudaMemcpyAsync(wb + 768, bte, 768UL*4, cudaMemcpyDeviceToDevice);
    conv_w_k<<<768, 256>>>(Wbl, whf);
    pack_w_k<<<384, 256>>>(Wcq, wcqp, 128);
    pack_w_k<<<384, 256>>>(Weq, weqp, 128);
    pack_w_k<<<768, 256>>>(Whe, wcatp, 768);
    pack_w_k<<<768, 256>>>(Wte, wcatp + 768UL*768, 768);
    pack_w_k<<<512, 256>>>(Wpp, wppp, 768);
    pack_w3_k<<<dim3(384, 3), 256>>>(Wgq, Wgk, Wgv, wqkvp, 768, 384L*768);
    pack_w_k<<<1152, 256>>>(Wp1, wp1p, 768);
    pack_kdim_k<<<dim3(256, 4), 256>>>(seq, seqp, 512, 256, 768);

    // 1) entity gathers
    ent_emb_k<<<Bn * NEn * MMn, 256>>>(seq, midx, mmask, ent_emb);
    ent_att_k<<<Bn * NEn * NHn, 512>>>(att, midx, mmask, ent_att);
    // 2) pair context attention
    ht_att_k<<<BPn, 512>>>(ent_att, hts, ht_att);
    // 3) rs = ht_att @ seq (fp16, seq packed)
    gemm_f16w<false,false><<<dim3(12, 6, 4), 256, GF_SMEM>>>(ht_att, seqp, nullptr, rs,
        Pn, Hn, Cn, Cn, Hn, 380L*512, 256L*768, 380L*768, 0L);
    // 4) htq, ent_q (fp16 packed weights)
    gemm_f16w<true,false><<<dim3(2, 24, 1), 256, GF_SMEM>>>(rs, wcqp, bcq, htqb,
        BPn, QSn, Hn, Hn, QSn, 0, 0, 0, 0L);
    gemm_f16w<true,false><<<dim3(2, 29, 1), 256, GF_SMEM>>>(ent_emb, weqp, beq, ent_q,
        1840, QSn, Hn, Hn, QSn, 0, 0, 0, 0L);
    // 5) mention-pool softmax
    pool_attn_k<<<dim3(BPn, 2), 256>>>(htqb, ent_q, ent_emb, mmask, hts, hs_att, ts_att);
    // 6) hs/ts projections — z=2 batched fp16
    cat2_k<<<BPn, 256>>>(hs_att, ts_att, rs, cat_h, base + OFF_CAT_T);
    gemm_f16w<true,true><<<dim3(12, 24, 2), 256, GF_SMEM>>>(cat_h, wcatp, wb, hs_t,
        BPn, EMBn, 1536, 1536, EMBn, 1520L*1536, 768L*768, 1520L*768, 768L);
    // 7) grouped bilinear
    bilinear_tc<<<dim3(12, 12), 512, BL_SMEM>>>(hs_t, ts_t, whf, bbl, pairg, BPn);
    // 8) pos concat + Wpp (fp16)
    catpp_k<<<BPn, 256>>>(pairg, pos, hts, catpp);
    gemm_f16w<true,true><<<dim3(12, 24, 1), 256, GF_SMEM>>>(catpp, wppp, bpp, pair1,
        BPn, EMBn, 1024, 1024, EMBn, 0, 0, 0, 0L);
    // 9) pair-graph attention: q/k/v fp16 z=3; pack qb|kb + vb; sc fp16; atto fp16
    gemm_f16w<false,false><<<dim3(12, 24, 3), 256, GF_SMEM>>>(pair1, wqkvp, nullptr, qb,
        BPn, EMBn, EMBn, EMBn, EMBn, 0, 384L*768, 1520L*768, 0L);
    pack_rows_k<<<3040, 256>>>(qb, qkp, 768);
    pack_kdim_k<<<dim3(192, 4), 256>>>(vb, vbp, 380, 192, 768);
    gemm_f16sc<<<dim3(6, 6, 4), 256, GS_SMEM>>>(qkp, qkp + 1520L*384, scb,
        Pn, Pn, EMBn, 384, 380L*384, 380L*384, 380L*380, SCALE_EMB);
    pair_softmax_k<<<BPn, 128>>>(scb, vis);
    gemm_f16w<false,false><<<dim3(12, 6, 4), 256, GF_SMEM>>>(scb, vbp, nullptr, atto,
        Pn, EMBn, Pn, Pn, EMBn, 380L*380, 192L*768, 380L*768, 0L);
    // 10) classifier head: Wp1 fp16, Wp2 tf32 (N=97)
    catfeat_k<<<BPn, 256>>>(hs_t, ts_t, pair1, atto, catf);
    gemm_f16w<true,true><<<dim3(12, 24, 1), 256, GF_SMEM>>>(catf, wp1p, bp1, h1,
        BPn, EMBn, 2304, 2304, EMBn, 0, 0, 0, 0L);
    gemm_tc<false,true,false><<<dim3(2, 24, 1), 256, GT_SMEM>>>(h1, Wp2, bp2, out,
        BPn, NCLSn, EMBn, EMBn, NCLSn, NCLSn, 0, 0, 0, 1.f, 0L);
}